// round 10
// baseline (speedup 1.0000x reference)
#include <cuda_runtime.h>
#include <cuda_fp16.h>
#include <cstdint>

#define T_LEN   4096
#define D_MODEL 1024
#define NHEAD   8
#define HDIM    128
#define ATTN_SCALE 0.12f

// ---------------- fp16 mma helpers -------------------------------------------
__device__ __forceinline__ void mma_f16(float* d,
    unsigned a0, unsigned a1, unsigned a2, unsigned a3,
    unsigned b0, unsigned b1) {
    asm volatile("mma.sync.aligned.m16n8k16.row.col.f32.f16.f16.f32 "
        "{%0,%1,%2,%3},{%4,%5,%6,%7},{%8,%9},{%0,%1,%2,%3};"
        : "+f"(d[0]), "+f"(d[1]), "+f"(d[2]), "+f"(d[3])
        : "r"(a0), "r"(a1), "r"(a2), "r"(a3), "r"(b0), "r"(b1));
}
// pack two f32 -> f16x2 word {lo, hi}. PTX: cvt d, a, b -> hi=a, lo=b.
__device__ __forceinline__ unsigned f2h2(float lo, float hi) {
    unsigned r;
    asm("cvt.rn.f16x2.f32 %0, %1, %2;" : "=r"(r) : "f"(hi), "f"(lo));
    return r;
}
__device__ __forceinline__ float fexp(float x) {
    float t = x * 1.4426950408889634f;
    float f = floorf(t);
    float r = t - f;
    float p = 1.3400000e-3f;
    p = fmaf(p, r, 9.6770508e-3f);
    p = fmaf(p, r, 5.5503310e-2f);
    p = fmaf(p, r, 2.4022652e-1f);
    p = fmaf(p, r, 6.9314718e-1f);
    p = fmaf(p, r, 1.0f);
    int e = (int)f;
    e = max(e, -127);
    float s = __int_as_float((unsigned)(e + 127) << 23);
    return p * s;
}
__device__ __forceinline__ void cp16(void* smem_ptr, const void* gptr) {
    unsigned sa = (unsigned)__cvta_generic_to_shared(smem_ptr);
    asm volatile("cp.async.cg.shared.global [%0], [%1], 16;" :: "r"(sa), "l"(gptr));
}
#define CP_COMMIT() asm volatile("cp.async.commit_group;")
#define CP_WAIT(N)  asm volatile("cp.async.wait_group %0;" :: "n"(N))

// ---------------- scratch (word = fp16x2) -------------------------------------
__device__ float    g_qkv[(size_t)T_LEN * 3 * D_MODEL];          // fp32 gemm out
__device__ unsigned g_q[(size_t)NHEAD * T_LEN * (HDIM / 2)];     // fp16 words, perm, *scale
__device__ unsigned g_k[(size_t)NHEAD * T_LEN * (HDIM / 2)];     // fp16 words, perm
__device__ unsigned g_v[(size_t)NHEAD * HDIM * (T_LEN / 2)];     // V^T fp16 words, s-perm
__device__ unsigned g_y[(size_t)T_LEN * (D_MODEL / 2)];          // fp16 words, perm
__device__ unsigned g_xi[(size_t)T_LEN * (D_MODEL / 2)];
__device__ unsigned g_wi[(size_t)3 * D_MODEL * (D_MODEL / 2)];
__device__ unsigned g_cpi[(size_t)D_MODEL * (D_MODEL / 2)];

// ---------------- pre-pass: fp32 -> fp16 words, permuted within 16-elem groups
__global__ __launch_bounds__(256) void conv_h(const float* __restrict__ in,
                                              unsigned* __restrict__ out, int ng) {
    int g = blockIdx.x * 256 + threadIdx.x;
    if (g >= ng) return;
    const float4* ip = (const float4*)(in + (size_t)g * 16);
    float4 v0 = ip[0], v1 = ip[1], v2 = ip[2], v3 = ip[3];
    unsigned w0 = f2h2(v0.x, v0.y), w1 = f2h2(v0.z, v0.w);
    unsigned w2 = f2h2(v1.x, v1.y), w3 = f2h2(v1.z, v1.w);
    unsigned w4 = f2h2(v2.x, v2.y), w5 = f2h2(v2.z, v2.w);
    unsigned w6 = f2h2(v3.x, v3.y), w7 = f2h2(v3.z, v3.w);
    uint4 o0; o0.x = w0; o0.y = w4; o0.z = w1; o0.w = w5;
    uint4 o1; o1.x = w2; o1.y = w6; o1.z = w3; o1.w = w7;
    uint4* op = (uint4*)(out + (size_t)g * 8);
    op[0] = o0; op[1] = o1;
}

// ---------------- fp16 NT GEMM: C[M,N] = A[M,K] B[N,K]^T ----------------------
#define GST 20
#define GSTAGE (128 * GST)
#define GEMM_SMEM (4 * 2 * GSTAGE * 4)
__global__ __launch_bounds__(256, 2) void gemm_h(const unsigned* __restrict__ A,
                                                 const unsigned* __restrict__ B,
                                                 float* __restrict__ C,
                                                 int M, int N, int Kw) {
    extern __shared__ unsigned smu[];
    const int bm = blockIdx.y * 128, bn = blockIdx.x * 128;
    const int tid = threadIdx.x;
    const int wid = tid >> 5, lane = tid & 31;
    const int wm = (wid >> 1) * 32, wn = (wid & 1) * 64;
    const int lq = lane >> 2, lr = lane & 3;

    float acc[2][8][4];
#pragma unroll
    for (int mf = 0; mf < 2; mf++)
#pragma unroll
        for (int nf = 0; nf < 8; nf++)
#pragma unroll
            for (int j = 0; j < 4; j++) acc[mf][nf][j] = 0.f;

    const int nk = Kw >> 4;

    auto issue = [&](int it, int buf) {
        unsigned* sA = smu + buf * (2 * GSTAGE);
        unsigned* sB = sA + GSTAGE;
        int k0 = it << 4;
#pragma unroll
        for (int p = 0; p < 2; p++) {
            int e = tid + 256 * p;
            int r = e >> 2, ch = (e & 3) * 4;
            cp16(&sA[r * GST + ch], A + (size_t)(bm + r) * Kw + k0 + ch);
            cp16(&sB[r * GST + ch], B + (size_t)(bn + r) * Kw + k0 + ch);
        }
    };

    issue(0, 0); CP_COMMIT();
    issue(1, 1); CP_COMMIT();
    issue(2, 2); CP_COMMIT();

    for (int it = 0; it < nk; it++) {
        CP_WAIT(2);
        __syncthreads();
        if (it + 3 < nk) issue(it + 3, (it + 3) & 3);
        CP_COMMIT();

        const unsigned* sA = smu + (it & 3) * (2 * GSTAGE);
        const unsigned* sB = sA + GSTAGE;
#pragma unroll
        for (int ks = 0; ks < 2; ks++) {
            unsigned a[2][4];
#pragma unroll
            for (int mf = 0; mf < 2; mf++) {
                uint2 a02 = *(const uint2*)&sA[(wm + mf * 16 + lq) * GST + ks * 8 + lr * 2];
                uint2 a13 = *(const uint2*)&sA[(wm + mf * 16 + 8 + lq) * GST + ks * 8 + lr * 2];
                a[mf][0] = a02.x; a[mf][1] = a13.x; a[mf][2] = a02.y; a[mf][3] = a13.y;
            }
#pragma unroll
            for (int nf = 0; nf < 8; nf++) {
                uint2 b = *(const uint2*)&sB[(wn + nf * 8 + lq) * GST + ks * 8 + lr * 2];
                mma_f16(acc[0][nf], a[0][0], a[0][1], a[0][2], a[0][3], b.x, b.y);
                mma_f16(acc[1][nf], a[1][0], a[1][1], a[1][2], a[1][3], b.x, b.y);
            }
        }
    }
#pragma unroll
    for (int mf = 0; mf < 2; mf++)
#pragma unroll
        for (int nf = 0; nf < 8; nf++) {
            float* c0 = C + (size_t)(bm + wm + mf * 16 + lq) * N + bn + wn + nf * 8 + lr * 2;
            c0[0] = acc[mf][nf][0]; c0[1] = acc[mf][nf][1];
            float* c1 = c0 + 8 * (size_t)N;
            c1[0] = acc[mf][nf][2]; c1[1] = acc[mf][nf][3];
        }
}

// ---------------- RMSNorm + rotary + V blend -> fp16 Q/K (perm) + V^T ---------
__global__ __launch_bounds__(128) void qkv_post(const float* __restrict__ qkv,
                                                const float* __restrict__ ve,
                                                const float* __restrict__ lambdas,
                                                unsigned* __restrict__ Qw,
                                                unsigned* __restrict__ Kw,
                                                unsigned* __restrict__ Vtw) {
    const int t = blockIdx.x, h = blockIdx.y, d = threadIdx.x;
    const int lane = d & 31, wid = d >> 5;
    const float* base = qkv + (size_t)t * (3 * D_MODEL) + h * HDIM;

    float qv = base[d];
    float kv = base[D_MODEL + d];
    float vv = base[2 * D_MODEL + d];

    float s1 = qv * qv, s2 = kv * kv;
#pragma unroll
    for (int o = 16; o; o >>= 1) {
        s1 += __shfl_xor_sync(0xffffffffu, s1, o);
        s2 += __shfl_xor_sync(0xffffffffu, s2, o);
    }
    __shared__ float w1[4], w2[4];
    if (lane == 0) { w1[wid] = s1; w2[wid] = s2; }
    __syncthreads();
    float sq = w1[0] + w1[1] + w1[2] + w1[3];
    float sk = w2[0] + w2[1] + w2[2] + w2[3];
    const float eps = 1.1920929e-7f;
    float rq = rsqrtf(sq * (1.0f / 128.0f) + eps);
    float rk = rsqrtf(sk * (1.0f / 128.0f) + eps);

    __shared__ float qs[128], ks[128];
    qs[d] = qv * rq; ks[d] = kv * rk;
    __syncthreads();

    int j = d & 63;
    float ang = (j < 32) ? exp2f((float)j * (-10.0f / 31.0f)) : 0.0f;
    float theta = (float)t * ang;
    float c, s;
    sincosf(theta, &s, &c);

    float qo, ko;
    if (d < 64) {
        qo =  qs[d] * c + qs[d + 64] * s;
        ko =  ks[d] * c + ks[d + 64] * s;
    } else {
        qo = -qs[d - 64] * s + qs[d] * c;
        ko = -ks[d - 64] * s + ks[d] * c;
    }

    float l0 = lambdas[0], l1 = lambdas[1];
    float vo = l0 * vv + l1 * ve[(size_t)t * D_MODEL + h * HDIM + d];

    // V^T [h][d][t], fp16, word-permuted along s within 16-s groups
    {
        int ws = t >> 1;
        int gg = ws >> 3, pp = ws & 7;
        int iw = (gg << 3) | (((pp & 3) << 1) | (pp >> 2));
        size_t widx = ((size_t)(h * HDIM + d)) * (T_LEN / 2) + iw;
        ((__half*)Vtw)[widx * 2 + (t & 1)] = __float2half_rn(vo);
    }

    __syncthreads();                 // rotary reads of qs/ks done
    qs[d] = qo * ATTN_SCALE;
    ks[d] = ko;
    __syncthreads();

    if (d < 64) {                    // pack word w=d (elems 2d, 2d+1), permuted
        int p = d & 7, g = d >> 3;
        int iw = (g << 3) | (((p & 3) << 1) | (p >> 2));
        size_t rbw = ((size_t)h * T_LEN + t) * (HDIM / 2);
        Qw[rbw + iw] = f2h2(qs[2 * d], qs[2 * d + 1]);
        Kw[rbw + iw] = f2h2(ks[2 * d], ks[2 * d + 1]);
    }
}

// ---------------- fp16 mma causal flash attention (2 CTAs/SM) ------------------
// 256 thr, 8 warps, CTA = 128 q rows, 64-key tiles, double-buffered K & V^T.
// Q staged in smem (read per tile); P register-resident.
#define QS  68                        // Q tile row stride (64 words + 4)
#define QW  (128 * QS)
#define KS  68                        // K tile row stride
#define KW  (64 * KS)
#define VTS 36                        // V^T tile row stride (32 words + 4)
#define VW  (128 * VTS)
#define ATTN_SMEM ((QW + 2 * KW + 2 * VW) * 4)
__global__ __launch_bounds__(256, 2) void attn_h(const unsigned* __restrict__ Q,
                                                 const unsigned* __restrict__ K,
                                                 const unsigned* __restrict__ Vt,
                                                 unsigned* __restrict__ Y) {
    extern __shared__ unsigned sm[];
    unsigned* Qs = sm;                       // [128][QS]
    unsigned* Kbase = sm + QW;               // 2 x [64][KS]
    unsigned* Vbase = sm + QW + 2 * KW;      // 2 x [128][VTS]

    const int h  = blockIdx.y;
    const int qb = ((int)gridDim.x - 1 - (int)blockIdx.x) * 128;
    const int tid = threadIdx.x, wid = tid >> 5, lane = tid & 31;
    const int lq = lane >> 2, lr = lane & 3;
    const int qw = wid * 16;

    const unsigned* Qhw = Q + (size_t)h * T_LEN * (HDIM / 2);
    const unsigned* Khw = K + (size_t)h * T_LEN * (HDIM / 2);
    const unsigned* Vtwh = Vt + (size_t)h * HDIM * (T_LEN / 2);

    // stage Q tile (128 x 64 words) via cp.async
#pragma unroll
    for (int p = 0; p < 8; p++) {
        int e = tid + 256 * p;
        int r = e >> 4, c = (e & 15) * 4;
        cp16(&Qs[r * QS + c], Qhw + (size_t)(qb + r) * (HDIM / 2) + c);
    }

    auto issue_kv = [&](int s0, int buf) {
        unsigned* Kb = Kbase + buf * KW;
        unsigned* Vb = Vbase + buf * VW;
        const int s0w = s0 >> 1;
#pragma unroll
        for (int p = 0; p < 4; p++) {
            int e = tid + 256 * p;
            int rk = e >> 4, ck = (e & 15) * 4;
            cp16(&Kb[rk * KS + ck], Khw + (size_t)(s0 + rk) * (HDIM / 2) + ck);
            int rv = e >> 3, cv = (e & 7) * 4;
            cp16(&Vb[rv * VTS + cv], Vtwh + (size_t)rv * (T_LEN / 2) + s0w + cv);
        }
    };

    issue_kv(0, 0); CP_COMMIT();             // Q + first K/V in one group

    float ofr[16][4];
#pragma unroll
    for (int nf = 0; nf < 16; nf++)
#pragma unroll
        for (int j = 0; j < 4; j++) ofr[nf][j] = 0.f;
    float m0 = -1e30f, m1 = -1e30f, l0 = 0.f, l1 = 0.f;

    const int ntiles = qb / 64 + 2;
    const unsigned* Qr0 = &Qs[(qw + lq) * QS];
    const unsigned* Qr1 = &Qs[(qw + 8 + lq) * QS];

    for (int it = 0; it < ntiles; it++) {
        const int s0 = it * 64;
        const int buf = it & 1;
        CP_WAIT(0);
        __syncthreads();                     // Q (first iter) + K,V(buf) visible
        if (it + 1 < ntiles) issue_kv(s0 + 64, buf ^ 1);
        CP_COMMIT();

        const unsigned* Kb = Kbase + buf * KW;
        const unsigned* Vb = Vbase + buf * VW;

        // ---- S = Q K^T (warp rows qw..qw+15), Q frags from smem ----
        float sfr[8][4];
#pragma unroll
        for (int nf = 0; nf < 8; nf++)
#pragma unroll
            for (int j = 0; j < 4; j++) sfr[nf][j] = 0.f;
#pragma unroll
        for (int ks = 0; ks < 8; ks++) {
            uint2 a02 = *(const uint2*)&Qr0[ks * 8 + lr * 2];
            uint2 a13 = *(const uint2*)&Qr1[ks * 8 + lr * 2];
#pragma unroll
            for (int nf = 0; nf < 8; nf++) {
                uint2 b = *(const uint2*)&Kb[(nf * 8 + lq) * KS + ks * 8 + lr * 2];
                mma_f16(sfr[nf], a02.x, a13.x, a02.y, a13.y, b.x, b.y);
            }
        }

        // ---- masked online softmax (warp-local, P stays in registers) ----
        const int q0 = qb + qw + lq, q1 = q0 + 8;
        const bool needmask = (s0 + 63) > (qb + qw);
        float r0 = -1e30f, r1 = -1e30f;
        if (needmask) {
#pragma unroll
            for (int nf = 0; nf < 8; nf++) {
                int sA = s0 + nf * 8 + 2 * lr, sB = sA + 1;
                if (sA > q0) sfr[nf][0] = -1e30f;
                if (sB > q0) sfr[nf][1] = -1e30f;
                if (sA > q1) sfr[nf][2] = -1e30f;
                if (sB > q1) sfr[nf][3] = -1e30f;
            }
        }
#pragma unroll
        for (int nf = 0; nf < 8; nf++) {
            r0 = fmaxf(r0, fmaxf(sfr[nf][0], sfr[nf][1]));
            r1 = fmaxf(r1, fmaxf(sfr[nf][2], sfr[nf][3]));
        }
        r0 = fmaxf(r0, __shfl_xor_sync(0xffffffffu, r0, 1));
        r0 = fmaxf(r0, __shfl_xor_sync(0xffffffffu, r0, 2));
        r1 = fmaxf(r1, __shfl_xor_sync(0xffffffffu, r1, 1));
        r1 = fmaxf(r1, __shfl_xor_sync(0xffffffffu, r1, 2));
        float mn0 = fmaxf(m0, r0), mn1 = fmaxf(m1, r1);
        float rs0 = fexp(m0 - mn0), rs1 = fexp(m1 - mn1);
        float sum0 = 0.f, sum1 = 0.f;
        unsigned pu0[8], pu1[8];
#pragma unroll
        for (int nf = 0; nf < 8; nf++) {
            float p00 = fexp(sfr[nf][0] - mn0);
            float p01 = fexp(sfr[nf][1] - mn0);
            float p10 = fexp(sfr[nf][2] - mn1);
            float p11 = fexp(sfr[nf][3] - mn1);
            sum0 += p00 + p01; sum1 += p10 + p11;
            pu0[nf] = f2h2(p00, p01);
            pu1[nf] = f2h2(p10, p11);
        }
        sum0 += __shfl_xor_sync(0xffffffffu, sum0, 1);
        sum0 += __shfl_xor_sync(0xffffffffu, sum0, 2);
        sum1 += __shfl_xor_sync(0xffffffffu, sum1, 1);
        sum1 += __shfl_xor_sync(0xffffffffu, sum1, 2);
        l0 = l0 * rs0 + sum0; m0 = mn0;
        l1 = l1 * rs1 + sum1; m1 = mn1;

        // ---- rescale O ----
#pragma unroll
        for (int nf = 0; nf < 16; nf++) {
            ofr[nf][0] *= rs0; ofr[nf][1] *= rs0;
            ofr[nf][2] *= rs1; ofr[nf][3] *= rs1;
        }

        // ---- O += P V : A = P (register-resident), B = V^T rows ------------
#pragma unroll
        for (int kk = 0; kk < 4; kk++) {
            unsigned a0 = pu0[2 * kk],     a1 = pu1[2 * kk];
            unsigned a2 = pu0[2 * kk + 1], a3 = pu1[2 * kk + 1];
#pragma unroll
            for (int nf = 0; nf < 16; nf++) {
                uint2 b = *(const uint2*)&Vb[(nf * 8 + lq) * VTS + kk * 8 + lr * 2];
                mma_f16(ofr[nf], a0, a1, a2, a3, b.x, b.y);
            }
        }
    }

    // ---- epilogue: normalize, fp16-pack, group-permuted into Y ---------------
    float inv0 = 1.0f / l0, inv1 = 1.0f / l1;
    unsigned* ya = Y + (size_t)(qb + qw + lq) * (D_MODEL / 2) + h * (HDIM / 2);
    unsigned* yb = ya + 8 * (size_t)(D_MODEL / 2);
#pragma unroll
    for (int nf = 0; nf < 16; nf++) {
        int off = (nf >> 1) * 8 + 2 * lr + (nf & 1);   // permuted word pos
        ya[off] = f2h2(ofr[nf][0] * inv0, ofr[nf][1] * inv0);
        yb[off] = f2h2(ofr[nf][2] * inv1, ofr[nf][3] * inv1);
    }
}

// ---------------- launch ------------------------------------------------------
extern "C" void kernel_launch(void* const* d_in, const int* in_sizes, int n_in,
                              void* d_out, int out_size) {
    const float* x        = (const float*)d_in[0];
    const float* ve       = (const float*)d_in[1];
    const float* qkv_w    = (const float*)d_in[2];
    const float* lambdas  = (const float*)d_in[3];
    const float* c_proj_w = (const float*)d_in[4];
    float* out = (float*)d_out;

    float* p_qkv;
    unsigned *p_q, *p_k, *p_v, *p_y, *p_xi, *p_wi, *p_cpi;
    cudaGetSymbolAddress((void**)&p_qkv, g_qkv);
    cudaGetSymbolAddress((void**)&p_q, g_q);
    cudaGetSymbolAddress((void**)&p_k, g_k);
    cudaGetSymbolAddress((void**)&p_v, g_v);
    cudaGetSymbolAddress((void**)&p_y, g_y);
    cudaGetSymbolAddress((void**)&p_xi, g_xi);
    cudaGetSymbolAddress((void**)&p_wi, g_wi);
    cudaGetSymbolAddress((void**)&p_cpi, g_cpi);

    static bool attr_set = false;
    if (!attr_set) {
        cudaFuncSetAttribute(gemm_h, cudaFuncAttributeMaxDynamicSharedMemorySize,
                             GEMM_SMEM);
        cudaFuncSetAttribute(attn_h, cudaFuncAttributeMaxDynamicSharedMemorySize,
                             ATTN_SMEM);
        attr_set = true;
    }

    // pre-pass conversions (fp32 -> permuted fp16 words)
    conv_h<<<1024, 256>>>(x, p_xi, T_LEN * D_MODEL / 16);
    conv_h<<<768, 256>>>(qkv_w, p_wi, 3 * D_MODEL * D_MODEL / 16);
    conv_h<<<256, 256>>>(c_proj_w, p_cpi, D_MODEL * D_MODEL / 16);

    // QKV projection
    gemm_h<<<dim3(3 * D_MODEL / 128, T_LEN / 128), 256, GEMM_SMEM>>>(
        p_xi, p_wi, p_qkv, T_LEN, 3 * D_MODEL, D_MODEL / 2);

    qkv_post<<<dim3(T_LEN, NHEAD), 128>>>(p_qkv, ve, lambdas, p_q, p_k, p_v);

    attn_h<<<dim3(T_LEN / 128, NHEAD), 256, ATTN_SMEM>>>(p_q, p_k, p_v, p_y);

    // output projection
    gemm_h<<<dim3(D_MODEL / 128, T_LEN / 128), 256, GEMM_SMEM>>>(
        p_y, p_cpi, out, T_LEN, D_MODEL, D_MODEL / 2);
}

// round 12
// speedup vs baseline: 1.3005x; 1.3005x over previous
#include <cuda_runtime.h>
#include <cuda_fp16.h>
#include <cstdint>

#define T_LEN   4096
#define D_MODEL 1024
#define NHEAD   8
#define HDIM    128
#define ATTN_SCALE 0.12f

// ---------------- fp16 mma helpers -------------------------------------------
__device__ __forceinline__ void mma_f16(float* d,
    unsigned a0, unsigned a1, unsigned a2, unsigned a3,
    unsigned b0, unsigned b1) {
    asm volatile("mma.sync.aligned.m16n8k16.row.col.f32.f16.f16.f32 "
        "{%0,%1,%2,%3},{%4,%5,%6,%7},{%8,%9},{%0,%1,%2,%3};"
        : "+f"(d[0]), "+f"(d[1]), "+f"(d[2]), "+f"(d[3])
        : "r"(a0), "r"(a1), "r"(a2), "r"(a3), "r"(b0), "r"(b1));
}
// pack two f32 -> f16x2 word {lo, hi}. PTX: cvt d, a, b -> hi=a, lo=b.
__device__ __forceinline__ unsigned f2h2(float lo, float hi) {
    unsigned r;
    asm("cvt.rn.f16x2.f32 %0, %1, %2;" : "=r"(r) : "f"(hi), "f"(lo));
    return r;
}
// fast exp: 1 MUL + 1 MUFU.EX2 (large negative -> 0)
__device__ __forceinline__ float fexp(float x) { return __expf(x); }

__device__ __forceinline__ void cp16(void* smem_ptr, const void* gptr) {
    unsigned sa = (unsigned)__cvta_generic_to_shared(smem_ptr);
    asm volatile("cp.async.cg.shared.global [%0], [%1], 16;" :: "r"(sa), "l"(gptr));
}
#define CP_COMMIT() asm volatile("cp.async.commit_group;")
#define CP_WAIT(N)  asm volatile("cp.async.wait_group %0;" :: "n"(N))

// ---------------- scratch (word = fp16x2) -------------------------------------
__device__ float    g_qkv[(size_t)T_LEN * 3 * D_MODEL];          // fp32 gemm out
__device__ unsigned g_q[(size_t)NHEAD * T_LEN * (HDIM / 2)];     // fp16 words, perm, *scale
__device__ unsigned g_k[(size_t)NHEAD * T_LEN * (HDIM / 2)];     // fp16 words, perm
__device__ unsigned g_v[(size_t)NHEAD * HDIM * (T_LEN / 2)];     // V^T fp16 words, s-perm
__device__ unsigned g_y[(size_t)T_LEN * (D_MODEL / 2)];          // fp16 words, perm
__device__ unsigned g_xi[(size_t)T_LEN * (D_MODEL / 2)];
__device__ unsigned g_wi[(size_t)3 * D_MODEL * (D_MODEL / 2)];
__device__ unsigned g_cpi[(size_t)D_MODEL * (D_MODEL / 2)];

// ---------------- pre-pass: fp32 -> fp16 words, permuted within 16-elem groups
__global__ __launch_bounds__(256) void conv_h(const float* __restrict__ in,
                                              unsigned* __restrict__ out, int ng) {
    int g = blockIdx.x * 256 + threadIdx.x;
    if (g >= ng) return;
    const float4* ip = (const float4*)(in + (size_t)g * 16);
    float4 v0 = ip[0], v1 = ip[1], v2 = ip[2], v3 = ip[3];
    unsigned w0 = f2h2(v0.x, v0.y), w1 = f2h2(v0.z, v0.w);
    unsigned w2 = f2h2(v1.x, v1.y), w3 = f2h2(v1.z, v1.w);
    unsigned w4 = f2h2(v2.x, v2.y), w5 = f2h2(v2.z, v2.w);
    unsigned w6 = f2h2(v3.x, v3.y), w7 = f2h2(v3.z, v3.w);
    uint4 o0; o0.x = w0; o0.y = w4; o0.z = w1; o0.w = w5;
    uint4 o1; o1.x = w2; o1.y = w6; o1.z = w3; o1.w = w7;
    uint4* op = (uint4*)(out + (size_t)g * 8);
    op[0] = o0; op[1] = o1;
}

// ---------------- fp16 NT GEMM: C[M,N] = A[M,K] B[N,K]^T ----------------------
#define GST 20
#define GSTAGE (128 * GST)
#define GEMM_SMEM (4 * 2 * GSTAGE * 4)
__global__ __launch_bounds__(256, 2) void gemm_h(const unsigned* __restrict__ A,
                                                 const unsigned* __restrict__ B,
                                                 float* __restrict__ C,
                                                 int M, int N, int Kw) {
    extern __shared__ unsigned smu[];
    const int bm = blockIdx.y * 128, bn = blockIdx.x * 128;
    const int tid = threadIdx.x;
    const int wid = tid >> 5, lane = tid & 31;
    const int wm = (wid >> 1) * 32, wn = (wid & 1) * 64;
    const int lq = lane >> 2, lr = lane & 3;

    float acc[2][8][4];
#pragma unroll
    for (int mf = 0; mf < 2; mf++)
#pragma unroll
        for (int nf = 0; nf < 8; nf++)
#pragma unroll
            for (int j = 0; j < 4; j++) acc[mf][nf][j] = 0.f;

    const int nk = Kw >> 4;

    auto issue = [&](int it, int buf) {
        unsigned* sA = smu + buf * (2 * GSTAGE);
        unsigned* sB = sA + GSTAGE;
        int k0 = it << 4;
#pragma unroll
        for (int p = 0; p < 2; p++) {
            int e = tid + 256 * p;
            int r = e >> 2, ch = (e & 3) * 4;
            cp16(&sA[r * GST + ch], A + (size_t)(bm + r) * Kw + k0 + ch);
            cp16(&sB[r * GST + ch], B + (size_t)(bn + r) * Kw + k0 + ch);
        }
    };

    issue(0, 0); CP_COMMIT();
    issue(1, 1); CP_COMMIT();
    issue(2, 2); CP_COMMIT();

    for (int it = 0; it < nk; it++) {
        CP_WAIT(2);
        __syncthreads();
        if (it + 3 < nk) issue(it + 3, (it + 3) & 3);
        CP_COMMIT();

        const unsigned* sA = smu + (it & 3) * (2 * GSTAGE);
        const unsigned* sB = sA + GSTAGE;
#pragma unroll
        for (int ks = 0; ks < 2; ks++) {
            unsigned a[2][4];
#pragma unroll
            for (int mf = 0; mf < 2; mf++) {
                uint2 a02 = *(const uint2*)&sA[(wm + mf * 16 + lq) * GST + ks * 8 + lr * 2];
                uint2 a13 = *(const uint2*)&sA[(wm + mf * 16 + 8 + lq) * GST + ks * 8 + lr * 2];
                a[mf][0] = a02.x; a[mf][1] = a13.x; a[mf][2] = a02.y; a[mf][3] = a13.y;
            }
#pragma unroll
            for (int nf = 0; nf < 8; nf++) {
                uint2 b = *(const uint2*)&sB[(wn + nf * 8 + lq) * GST + ks * 8 + lr * 2];
                mma_f16(acc[0][nf], a[0][0], a[0][1], a[0][2], a[0][3], b.x, b.y);
                mma_f16(acc[1][nf], a[1][0], a[1][1], a[1][2], a[1][3], b.x, b.y);
            }
        }
    }
#pragma unroll
    for (int mf = 0; mf < 2; mf++)
#pragma unroll
        for (int nf = 0; nf < 8; nf++) {
            float* c0 = C + (size_t)(bm + wm + mf * 16 + lq) * N + bn + wn + nf * 8 + lr * 2;
            c0[0] = acc[mf][nf][0]; c0[1] = acc[mf][nf][1];
            float* c1 = c0 + 8 * (size_t)N;
            c1[0] = acc[mf][nf][2]; c1[1] = acc[mf][nf][3];
        }
}

// ---------------- RMSNorm + rotary + V blend (2 tokens/block) -----------------
__global__ __launch_bounds__(256) void qkv_post(const float* __restrict__ qkv,
                                                const float* __restrict__ ve,
                                                const float* __restrict__ lambdas,
                                                unsigned* __restrict__ Qw,
                                                unsigned* __restrict__ Kw,
                                                unsigned* __restrict__ Vtw) {
    const int sb = threadIdx.x >> 7;          // sub-block: token within pair
    const int d  = threadIdx.x & 127;
    const int t  = blockIdx.x * 2 + sb;
    const int h  = blockIdx.y;
    const int lane = d & 31, wid = d >> 5;
    const float* base = qkv + (size_t)t * (3 * D_MODEL) + h * HDIM;

    float qv = base[d];
    float kv = base[D_MODEL + d];
    float vv = base[2 * D_MODEL + d];

    float s1 = qv * qv, s2 = kv * kv;
#pragma unroll
    for (int o = 16; o; o >>= 1) {
        s1 += __shfl_xor_sync(0xffffffffu, s1, o);
        s2 += __shfl_xor_sync(0xffffffffu, s2, o);
    }
    __shared__ float w1[2][4], w2[2][4];
    if (lane == 0) { w1[sb][wid] = s1; w2[sb][wid] = s2; }
    __syncthreads();
    float sq = w1[sb][0] + w1[sb][1] + w1[sb][2] + w1[sb][3];
    float sk = w2[sb][0] + w2[sb][1] + w2[sb][2] + w2[sb][3];
    const float eps = 1.1920929e-7f;
    float rq = rsqrtf(sq * (1.0f / 128.0f) + eps);
    float rk = rsqrtf(sk * (1.0f / 128.0f) + eps);

    __shared__ float qs[2][128], ks[2][128];
    qs[sb][d] = qv * rq; ks[sb][d] = kv * rk;
    __syncthreads();

    int j = d & 63;
    float ang = (j < 32) ? exp2f((float)j * (-10.0f / 31.0f)) : 0.0f;
    float theta = (float)t * ang;
    float c, s;
    sincosf(theta, &s, &c);

    float qo, ko;
    if (d < 64) {
        qo =  qs[sb][d] * c + qs[sb][d + 64] * s;
        ko =  ks[sb][d] * c + ks[sb][d + 64] * s;
    } else {
        qo = -qs[sb][d - 64] * s + qs[sb][d] * c;
        ko = -ks[sb][d - 64] * s + ks[sb][d] * c;
    }

    float l0 = lambdas[0], l1 = lambdas[1];
    float vo = l0 * vv + l1 * ve[(size_t)t * D_MODEL + h * HDIM + d];

    // V^T [h][d][t], fp16, word-permuted along s within 16-s groups
    {
        int ws = t >> 1;
        int gg = ws >> 3, pp = ws & 7;
        int iw = (gg << 3) | (((pp & 3) << 1) | (pp >> 2));
        size_t widx = ((size_t)(h * HDIM + d)) * (T_LEN / 2) + iw;
        ((__half*)Vtw)[widx * 2 + (t & 1)] = __float2half_rn(vo);
    }

    __syncthreads();                 // rotary reads of qs/ks done
    qs[sb][d] = qo * ATTN_SCALE;
    ks[sb][d] = ko;
    __syncthreads();

    if (d < 64) {                    // pack word w=d (elems 2d, 2d+1), permuted
        int p = d & 7, g = d >> 3;
        int iw = (g << 3) | (((p & 3) << 1) | (p >> 2));
        size_t rbw = ((size_t)h * T_LEN + t) * (HDIM / 2);
        Qw[rbw + iw] = f2h2(qs[sb][2 * d], qs[sb][2 * d + 1]);
        Kw[rbw + iw] = f2h2(ks[sb][2 * d], ks[sb][2 * d + 1]);
    }
}

// ---------------- fp16 mma causal flash attention ------------------------------
// 256 thr, 8 warps, CTA = 128 q rows, 64-key tiles, double-buffered K & V^T.
// Q frags persistent in registers (32 regs). P register-resident (no shfl).
#define KS  68                       // K tile row stride (64 words + 4)
#define KW  (64 * KS)
#define VTS 36                       // V^T tile row stride (32 words + 4)
#define VW  (128 * VTS)
#define ATTN_SMEM ((2 * KW + 2 * VW) * 4)
__global__ __launch_bounds__(256) void attn_h(const unsigned* __restrict__ Q,
                                              const unsigned* __restrict__ K,
                                              const unsigned* __restrict__ Vt,
                                              unsigned* __restrict__ Y) {
    extern __shared__ unsigned sm[];

    const int h  = blockIdx.y;
    const int qb = ((int)gridDim.x - 1 - (int)blockIdx.x) * 128;
    const int tid = threadIdx.x, wid = tid >> 5, lane = tid & 31;
    const int lq = lane >> 2, lr = lane & 3;
    const int qw = wid * 16;

    const unsigned* Khw = K + (size_t)h * T_LEN * (HDIM / 2);
    const unsigned* Vtwh = Vt + (size_t)h * HDIM * (T_LEN / 2);

    // persistent Q fragments: rows qb+qw+lq, +8 ; 8 k16-groups
    unsigned qa[8][4];
    {
        const unsigned* Qr0 = Q + ((size_t)h * T_LEN + qb + qw + lq) * (HDIM / 2);
        const unsigned* Qr1 = Qr0 + 8 * (HDIM / 2);
#pragma unroll
        for (int ks = 0; ks < 8; ks++) {
            uint2 a02 = *(const uint2*)&Qr0[ks * 8 + lr * 2];
            uint2 a13 = *(const uint2*)&Qr1[ks * 8 + lr * 2];
            qa[ks][0] = a02.x; qa[ks][1] = a13.x; qa[ks][2] = a02.y; qa[ks][3] = a13.y;
        }
    }

    float ofr[16][4];
#pragma unroll
    for (int nf = 0; nf < 16; nf++)
#pragma unroll
        for (int j = 0; j < 4; j++) ofr[nf][j] = 0.f;
    float m0 = -1e30f, m1 = -1e30f, l0 = 0.f, l1 = 0.f;

    const int ntiles = qb / 64 + 2;

    auto issue_kv = [&](int s0, int buf) {
        unsigned* Kb = sm + buf * KW;
        unsigned* Vb = sm + 2 * KW + buf * VW;
        const int s0w = s0 >> 1;
#pragma unroll
        for (int p = 0; p < 4; p++) {
            int e = tid + 256 * p;
            int rk = e >> 4, ck = (e & 15) * 4;
            cp16(&Kb[rk * KS + ck], Khw + (size_t)(s0 + rk) * (HDIM / 2) + ck);
            int rv = e >> 3, cv = (e & 7) * 4;
            cp16(&Vb[rv * VTS + cv], Vtwh + (size_t)rv * (T_LEN / 2) + s0w + cv);
        }
    };

    issue_kv(0, 0); CP_COMMIT();

    for (int it = 0; it < ntiles; it++) {
        const int s0 = it * 64;
        const int buf = it & 1;
        CP_WAIT(0);
        __syncthreads();                       // K,V (buf) visible; buf^1 free
        if (it + 1 < ntiles) issue_kv(s0 + 64, buf ^ 1);
        CP_COMMIT();

        const unsigned* Kb = sm + buf * KW;
        const unsigned* Vb = sm + 2 * KW + buf * VW;

        // ---- S = Q K^T (warp rows qw..qw+15) ----
        float sfr[8][4];
#pragma unroll
        for (int nf = 0; nf < 8; nf++)
#pragma unroll
            for (int j = 0; j < 4; j++) sfr[nf][j] = 0.f;
#pragma unroll
        for (int ks = 0; ks < 8; ks++) {
#pragma unroll
            for (int nf = 0; nf < 8; nf++) {
                uint2 b = *(const uint2*)&Kb[(nf * 8 + lq) * KS + ks * 8 + lr * 2];
                mma_f16(sfr[nf], qa[ks][0], qa[ks][1], qa[ks][2], qa[ks][3], b.x, b.y);
            }
        }

        // ---- masked online softmax (warp-local, P stays in registers) ----
        const int q0 = qb + qw + lq, q1 = q0 + 8;
        const bool needmask = (s0 + 63) > (qb + qw);
        float r0 = -1e30f, r1 = -1e30f;
        if (needmask) {
#pragma unroll
            for (int nf = 0; nf < 8; nf++) {
                int sA = s0 + nf * 8 + 2 * lr, sB = sA + 1;
                if (sA > q0) sfr[nf][0] = -1e30f;
                if (sB > q0) sfr[nf][1] = -1e30f;
                if (sA > q1) sfr[nf][2] = -1e30f;
                if (sB > q1) sfr[nf][3] = -1e30f;
            }
        }
#pragma unroll
        for (int nf = 0; nf < 8; nf++) {
            r0 = fmaxf(r0, fmaxf(sfr[nf][0], sfr[nf][1]));
            r1 = fmaxf(r1, fmaxf(sfr[nf][2], sfr[nf][3]));
        }
        r0 = fmaxf(r0, __shfl_xor_sync(0xffffffffu, r0, 1));
        r0 = fmaxf(r0, __shfl_xor_sync(0xffffffffu, r0, 2));
        r1 = fmaxf(r1, __shfl_xor_sync(0xffffffffu, r1, 1));
        r1 = fmaxf(r1, __shfl_xor_sync(0xffffffffu, r1, 2));
        float mn0 = fmaxf(m0, r0), mn1 = fmaxf(m1, r1);
        float rs0 = fexp(m0 - mn0), rs1 = fexp(m1 - mn1);
        float sum0 = 0.f, sum1 = 0.f;
        unsigned pu0[8], pu1[8];
#pragma unroll
        for (int nf = 0; nf < 8; nf++) {
            float p00 = fexp(sfr[nf][0] - mn0);
            float p01 = fexp(sfr[nf][1] - mn0);
            float p10 = fexp(sfr[nf][2] - mn1);
            float p11 = fexp(sfr[nf][3] - mn1);
            sum0 += p00 + p01; sum1 += p10 + p11;
            pu0[nf] = f2h2(p00, p01);
            pu1[nf] = f2h2(p10, p11);
        }
        sum0 += __shfl_xor_sync(0xffffffffu, sum0, 1);
        sum0 += __shfl_xor_sync(0xffffffffu, sum0, 2);
        sum1 += __shfl_xor_sync(0xffffffffu, sum1, 1);
        sum1 += __shfl_xor_sync(0xffffffffu, sum1, 2);
        l0 = l0 * rs0 + sum0; m0 = mn0;
        l1 = l1 * rs1 + sum1; m1 = mn1;

        // ---- rescale O ----
#pragma unroll
        for (int nf = 0; nf < 16; nf++) {
            ofr[nf][0] *= rs0; ofr[nf][1] *= rs0;
            ofr[nf][2] *= rs1; ofr[nf][3] *= rs1;
        }

        // ---- O += P V : A = P (register-resident), B = V^T rows ------------
#pragma unroll
        for (int kk = 0; kk < 4; kk++) {
            unsigned a0 = pu0[2 * kk],     a1 = pu1[2 * kk];
            unsigned a2 = pu0[2 * kk + 1], a3 = pu1[2 * kk + 1];
#pragma unroll
            for (int nf = 0; nf < 16; nf++) {
                uint2 b = *(const uint2*)&Vb[(nf * 8 + lq) * VTS + kk * 8 + lr * 2];
                mma_f16(ofr[nf], a0, a1, a2, a3, b.x, b.y);
            }
        }
    }

    // ---- epilogue: normalize, fp16-pack, group-permuted into Y ---------------
    float inv0 = 1.0f / l0, inv1 = 1.0f / l1;
    unsigned* ya = Y + (size_t)(qb + qw + lq) * (D_MODEL / 2) + h * (HDIM / 2);
    unsigned* yb = ya + 8 * (size_t)(D_MODEL / 2);
#pragma unroll
    for (int nf = 0; nf < 16; nf++) {
        int off = (nf >> 1) * 8 + 2 * lr + (nf & 1);   // permuted word pos
        ya[off] = f2h2(ofr[nf][0] * inv0, ofr[nf][1] * inv0);
        yb[off] = f2h2(ofr[nf][2] * inv1, ofr[nf][3] * inv1);
    }
}

// ---------------- launch ------------------------------------------------------
extern "C" void kernel_launch(void* const* d_in, const int* in_sizes, int n_in,
                              void* d_out, int out_size) {
    const float* x        = (const float*)d_in[0];
    const float* ve       = (const float*)d_in[1];
    const float* qkv_w    = (const float*)d_in[2];
    const float* lambdas  = (const float*)d_in[3];
    const float* c_proj_w = (const float*)d_in[4];
    float* out = (float*)d_out;

    float* p_qkv;
    unsigned *p_q, *p_k, *p_v, *p_y, *p_xi, *p_wi, *p_cpi;
    cudaGetSymbolAddress((void**)&p_qkv, g_qkv);
    cudaGetSymbolAddress((void**)&p_q, g_q);
    cudaGetSymbolAddress((void**)&p_k, g_k);
    cudaGetSymbolAddress((void**)&p_v, g_v);
    cudaGetSymbolAddress((void**)&p_y, g_y);
    cudaGetSymbolAddress((void**)&p_xi, g_xi);
    cudaGetSymbolAddress((void**)&p_wi, g_wi);
    cudaGetSymbolAddress((void**)&p_cpi, g_cpi);

    static bool attr_set = false;
    if (!attr_set) {
        cudaFuncSetAttribute(gemm_h, cudaFuncAttributeMaxDynamicSharedMemorySize,
                             GEMM_SMEM);
        cudaFuncSetAttribute(attn_h, cudaFuncAttributeMaxDynamicSharedMemorySize,
                             ATTN_SMEM);
        attr_set = true;
    }

    // pre-pass conversions (fp32 -> permuted fp16 words)
    conv_h<<<1024, 256>>>(x, p_xi, T_LEN * D_MODEL / 16);
    conv_h<<<768, 256>>>(qkv_w, p_wi, 3 * D_MODEL * D_MODEL / 16);
    conv_h<<<256, 256>>>(c_proj_w, p_cpi, D_MODEL * D_MODEL / 16);

    // QKV projection
    gemm_h<<<dim3(3 * D_MODEL / 128, T_LEN / 128), 256, GEMM_SMEM>>>(
        p_xi, p_wi, p_qkv, T_LEN, 3 * D_MODEL, D_MODEL / 2);

    qkv_post<<<dim3(T_LEN / 2, NHEAD), 256>>>(p_qkv, ve, lambdas, p_q, p_k, p_v);

    attn_h<<<dim3(T_LEN / 128, NHEAD), 256, ATTN_SMEM>>>(p_q, p_k, p_v, p_y);

    // output projection
    gemm_h<<<dim3(D_MODEL / 128, T_LEN / 128), 256, GEMM_SMEM>>>(
        p_y, p_cpi, out, T_LEN, D_MODEL, D_MODEL / 2);
}

// round 13
// speedup vs baseline: 1.3280x; 1.0211x over previous
#include <cuda_runtime.h>
#include <cuda_fp16.h>
#include <cstdint>

#define T_LEN   4096
#define D_MODEL 1024
#define NHEAD   8
#define HDIM    128
#define ATTN_SCALE 0.12f
#define CEXP    5.9f   // static softmax shift: |s| <= 15.36, exp(15.6-5.9) < fp16 max

// ---------------- fp16 mma helpers -------------------------------------------
__device__ __forceinline__ void mma_f16(float* d,
    unsigned a0, unsigned a1, unsigned a2, unsigned a3,
    unsigned b0, unsigned b1) {
    asm volatile("mma.sync.aligned.m16n8k16.row.col.f32.f16.f16.f32 "
        "{%0,%1,%2,%3},{%4,%5,%6,%7},{%8,%9},{%0,%1,%2,%3};"
        : "+f"(d[0]), "+f"(d[1]), "+f"(d[2]), "+f"(d[3])
        : "r"(a0), "r"(a1), "r"(a2), "r"(a3), "r"(b0), "r"(b1));
}
// pack two f32 -> f16x2 word {lo, hi}. PTX: cvt d, a, b -> hi=a, lo=b.
__device__ __forceinline__ unsigned f2h2(float lo, float hi) {
    unsigned r;
    asm("cvt.rn.f16x2.f32 %0, %1, %2;" : "=r"(r) : "f"(hi), "f"(lo));
    return r;
}
// fast exp: 1 MUL + 1 MUFU.EX2 (large negative -> 0)
__device__ __forceinline__ float fexp(float x) { return __expf(x); }

__device__ __forceinline__ void cp16(void* smem_ptr, const void* gptr) {
    unsigned sa = (unsigned)__cvta_generic_to_shared(smem_ptr);
    asm volatile("cp.async.cg.shared.global [%0], [%1], 16;" :: "r"(sa), "l"(gptr));
}
#define CP_COMMIT() asm volatile("cp.async.commit_group;")
#define CP_WAIT(N)  asm volatile("cp.async.wait_group %0;" :: "n"(N))

// ---------------- scratch (word = fp16x2) -------------------------------------
__device__ float    g_qkv[(size_t)T_LEN * 3 * D_MODEL];          // fp32 gemm out
__device__ unsigned g_q[(size_t)NHEAD * T_LEN * (HDIM / 2)];     // fp16 words, perm, *scale
__device__ unsigned g_k[(size_t)NHEAD * T_LEN * (HDIM / 2)];     // fp16 words, perm
__device__ unsigned g_v[(size_t)NHEAD * HDIM * (T_LEN / 2)];     // V^T fp16 words, s-perm
__device__ unsigned g_y[(size_t)T_LEN * (D_MODEL / 2)];          // fp16 words, perm
__device__ unsigned g_xi[(size_t)T_LEN * (D_MODEL / 2)];
__device__ unsigned g_wi[(size_t)3 * D_MODEL * (D_MODEL / 2)];
__device__ unsigned g_cpi[(size_t)D_MODEL * (D_MODEL / 2)];

// ---------------- pre-pass: fp32 -> fp16 words, permuted within 16-elem groups
__global__ __launch_bounds__(256) void conv_h(const float* __restrict__ in,
                                              unsigned* __restrict__ out, int ng) {
    int g = blockIdx.x * 256 + threadIdx.x;
    if (g >= ng) return;
    const float4* ip = (const float4*)(in + (size_t)g * 16);
    float4 v0 = ip[0], v1 = ip[1], v2 = ip[2], v3 = ip[3];
    unsigned w0 = f2h2(v0.x, v0.y), w1 = f2h2(v0.z, v0.w);
    unsigned w2 = f2h2(v1.x, v1.y), w3 = f2h2(v1.z, v1.w);
    unsigned w4 = f2h2(v2.x, v2.y), w5 = f2h2(v2.z, v2.w);
    unsigned w6 = f2h2(v3.x, v3.y), w7 = f2h2(v3.z, v3.w);
    uint4 o0; o0.x = w0; o0.y = w4; o0.z = w1; o0.w = w5;
    uint4 o1; o1.x = w2; o1.y = w6; o1.z = w3; o1.w = w7;
    uint4* op = (uint4*)(out + (size_t)g * 8);
    op[0] = o0; op[1] = o1;
}

// ---------------- fp16 NT GEMM: C[M,N] = A[M,K] B[N,K]^T ----------------------
#define GST 20
#define GSTAGE (128 * GST)
#define GEMM_SMEM (4 * 2 * GSTAGE * 4)
__global__ __launch_bounds__(256, 2) void gemm_h(const unsigned* __restrict__ A,
                                                 const unsigned* __restrict__ B,
                                                 float* __restrict__ C,
                                                 int M, int N, int Kw) {
    extern __shared__ unsigned smu[];
    const int bm = blockIdx.y * 128, bn = blockIdx.x * 128;
    const int tid = threadIdx.x;
    const int wid = tid >> 5, lane = tid & 31;
    const int wm = (wid >> 1) * 32, wn = (wid & 1) * 64;
    const int lq = lane >> 2, lr = lane & 3;

    float acc[2][8][4];
#pragma unroll
    for (int mf = 0; mf < 2; mf++)
#pragma unroll
        for (int nf = 0; nf < 8; nf++)
#pragma unroll
            for (int j = 0; j < 4; j++) acc[mf][nf][j] = 0.f;

    const int nk = Kw >> 4;

    auto issue = [&](int it, int buf) {
        unsigned* sA = smu + buf * (2 * GSTAGE);
        unsigned* sB = sA + GSTAGE;
        int k0 = it << 4;
#pragma unroll
        for (int p = 0; p < 2; p++) {
            int e = tid + 256 * p;
            int r = e >> 2, ch = (e & 3) * 4;
            cp16(&sA[r * GST + ch], A + (size_t)(bm + r) * Kw + k0 + ch);
            cp16(&sB[r * GST + ch], B + (size_t)(bn + r) * Kw + k0 + ch);
        }
    };

    issue(0, 0); CP_COMMIT();
    issue(1, 1); CP_COMMIT();
    issue(2, 2); CP_COMMIT();

    for (int it = 0; it < nk; it++) {
        CP_WAIT(2);
        __syncthreads();
        if (it + 3 < nk) issue(it + 3, (it + 3) & 3);
        CP_COMMIT();

        const unsigned* sA = smu + (it & 3) * (2 * GSTAGE);
        const unsigned* sB = sA + GSTAGE;
#pragma unroll
        for (int ks = 0; ks < 2; ks++) {
            unsigned a[2][4];
#pragma unroll
            for (int mf = 0; mf < 2; mf++) {
                uint2 a02 = *(const uint2*)&sA[(wm + mf * 16 + lq) * GST + ks * 8 + lr * 2];
                uint2 a13 = *(const uint2*)&sA[(wm + mf * 16 + 8 + lq) * GST + ks * 8 + lr * 2];
                a[mf][0] = a02.x; a[mf][1] = a13.x; a[mf][2] = a02.y; a[mf][3] = a13.y;
            }
#pragma unroll
            for (int nf = 0; nf < 8; nf++) {
                uint2 b = *(const uint2*)&sB[(wn + nf * 8 + lq) * GST + ks * 8 + lr * 2];
                mma_f16(acc[0][nf], a[0][0], a[0][1], a[0][2], a[0][3], b.x, b.y);
                mma_f16(acc[1][nf], a[1][0], a[1][1], a[1][2], a[1][3], b.x, b.y);
            }
        }
    }
#pragma unroll
    for (int mf = 0; mf < 2; mf++)
#pragma unroll
        for (int nf = 0; nf < 8; nf++) {
            float* c0 = C + (size_t)(bm + wm + mf * 16 + lq) * N + bn + wn + nf * 8 + lr * 2;
            c0[0] = acc[mf][nf][0]; c0[1] = acc[mf][nf][1];
            float* c1 = c0 + 8 * (size_t)N;
            c1[0] = acc[mf][nf][2]; c1[1] = acc[mf][nf][3];
        }
}

// ---------------- RMSNorm + rotary + V blend (2 tokens/block) -----------------
__global__ __launch_bounds__(256) void qkv_post(const float* __restrict__ qkv,
                                                const float* __restrict__ ve,
                                                const float* __restrict__ lambdas,
                                                unsigned* __restrict__ Qw,
                                                unsigned* __restrict__ Kw,
                                                unsigned* __restrict__ Vtw) {
    const int sb = threadIdx.x >> 7;          // sub-block: token within pair
    const int d  = threadIdx.x & 127;
    const int t  = blockIdx.x * 2 + sb;
    const int h  = blockIdx.y;
    const int lane = d & 31, wid = d >> 5;
    const float* base = qkv + (size_t)t * (3 * D_MODEL) + h * HDIM;

    float qv = base[d];
    float kv = base[D_MODEL + d];
    float vv = base[2 * D_MODEL + d];

    float s1 = qv * qv, s2 = kv * kv;
#pragma unroll
    for (int o = 16; o; o >>= 1) {
        s1 += __shfl_xor_sync(0xffffffffu, s1, o);
        s2 += __shfl_xor_sync(0xffffffffu, s2, o);
    }
    __shared__ float w1[2][4], w2[2][4];
    if (lane == 0) { w1[sb][wid] = s1; w2[sb][wid] = s2; }
    __syncthreads();
    float sq = w1[sb][0] + w1[sb][1] + w1[sb][2] + w1[sb][3];
    float sk = w2[sb][0] + w2[sb][1] + w2[sb][2] + w2[sb][3];
    const float eps = 1.1920929e-7f;
    float rq = rsqrtf(sq * (1.0f / 128.0f) + eps);
    float rk = rsqrtf(sk * (1.0f / 128.0f) + eps);

    __shared__ float qs[2][128], ks[2][128];
    qs[sb][d] = qv * rq; ks[sb][d] = kv * rk;
    __syncthreads();

    int j = d & 63;
    float ang = (j < 32) ? exp2f((float)j * (-10.0f / 31.0f)) : 0.0f;
    float theta = (float)t * ang;
    float c, s;
    sincosf(theta, &s, &c);

    float qo, ko;
    if (d < 64) {
        qo =  qs[sb][d] * c + qs[sb][d + 64] * s;
        ko =  ks[sb][d] * c + ks[sb][d + 64] * s;
    } else {
        qo = -qs[sb][d - 64] * s + qs[sb][d] * c;
        ko = -ks[sb][d - 64] * s + ks[sb][d] * c;
    }

    float l0 = lambdas[0], l1 = lambdas[1];
    float vo = l0 * vv + l1 * ve[(size_t)t * D_MODEL + h * HDIM + d];

    // V^T [h][d][t], fp16, word-permuted along s within 16-s groups
    {
        int ws = t >> 1;
        int gg = ws >> 3, pp = ws & 7;
        int iw = (gg << 3) | (((pp & 3) << 1) | (pp >> 2));
        size_t widx = ((size_t)(h * HDIM + d)) * (T_LEN / 2) + iw;
        ((__half*)Vtw)[widx * 2 + (t & 1)] = __float2half_rn(vo);
    }

    __syncthreads();                 // rotary reads of qs/ks done
    qs[sb][d] = qo * ATTN_SCALE;
    ks[sb][d] = ko;
    __syncthreads();

    if (d < 64) {                    // pack word w=d (elems 2d, 2d+1), permuted
        int p = d & 7, g = d >> 3;
        int iw = (g << 3) | (((p & 3) << 1) | (p >> 2));
        size_t rbw = ((size_t)h * T_LEN + t) * (HDIM / 2);
        Qw[rbw + iw] = f2h2(qs[sb][2 * d], qs[sb][2 * d + 1]);
        Kw[rbw + iw] = f2h2(ks[sb][2 * d], ks[sb][2 * d + 1]);
    }
}

// ---------------- fp16 mma causal flash attention ------------------------------
// 256 thr, 8 warps, CTA = 128 q rows, 64-key tiles, double-buffered K & V^T.
// Static softmax shift (scores bounded by 15.36): no online max, no rescale,
// sums reduced once in the epilogue. P register-resident.
#define KS  68                       // K tile row stride (64 words + 4)
#define KW  (64 * KS)
#define VTS 36                       // V^T tile row stride (32 words + 4)
#define VW  (128 * VTS)
#define ATTN_SMEM ((2 * KW + 2 * VW) * 4)
__global__ __launch_bounds__(256) void attn_h(const unsigned* __restrict__ Q,
                                              const unsigned* __restrict__ K,
                                              const unsigned* __restrict__ Vt,
                                              unsigned* __restrict__ Y) {
    extern __shared__ unsigned sm[];

    const int h  = blockIdx.y;
    const int qb = ((int)gridDim.x - 1 - (int)blockIdx.x) * 128;
    const int tid = threadIdx.x, wid = tid >> 5, lane = tid & 31;
    const int lq = lane >> 2, lr = lane & 3;
    const int qw = wid * 16;

    const unsigned* Khw = K + (size_t)h * T_LEN * (HDIM / 2);
    const unsigned* Vtwh = Vt + (size_t)h * HDIM * (T_LEN / 2);

    // persistent Q fragments: rows qb+qw+lq, +8 ; 8 k16-groups
    unsigned qa[8][4];
    {
        const unsigned* Qr0 = Q + ((size_t)h * T_LEN + qb + qw + lq) * (HDIM / 2);
        const unsigned* Qr1 = Qr0 + 8 * (HDIM / 2);
#pragma unroll
        for (int ks = 0; ks < 8; ks++) {
            uint2 a02 = *(const uint2*)&Qr0[ks * 8 + lr * 2];
            uint2 a13 = *(const uint2*)&Qr1[ks * 8 + lr * 2];
            qa[ks][0] = a02.x; qa[ks][1] = a13.x; qa[ks][2] = a02.y; qa[ks][3] = a13.y;
        }
    }

    float ofr[16][4];
#pragma unroll
    for (int nf = 0; nf < 16; nf++)
#pragma unroll
        for (int j = 0; j < 4; j++) ofr[nf][j] = 0.f;
    float l0 = 0.f, l1 = 0.f;        // per-thread partial sums (quad-reduced at end)

    const int ntiles = qb / 64 + 2;

    auto issue_kv = [&](int s0, int buf) {
        unsigned* Kb = sm + buf * KW;
        unsigned* Vb = sm + 2 * KW + buf * VW;
        const int s0w = s0 >> 1;
#pragma unroll
        for (int p = 0; p < 4; p++) {
            int e = tid + 256 * p;
            int rk = e >> 4, ck = (e & 15) * 4;
            cp16(&Kb[rk * KS + ck], Khw + (size_t)(s0 + rk) * (HDIM / 2) + ck);
            int rv = e >> 3, cv = (e & 7) * 4;
            cp16(&Vb[rv * VTS + cv], Vtwh + (size_t)rv * (T_LEN / 2) + s0w + cv);
        }
    };

    issue_kv(0, 0); CP_COMMIT();

    for (int it = 0; it < ntiles; it++) {
        const int s0 = it * 64;
        const int buf = it & 1;
        CP_WAIT(0);
        __syncthreads();                       // K,V (buf) visible; buf^1 free
        if (it + 1 < ntiles) issue_kv(s0 + 64, buf ^ 1);
        CP_COMMIT();

        const unsigned* Kb = sm + buf * KW;
        const unsigned* Vb = sm + 2 * KW + buf * VW;

        // ---- S = Q K^T (warp rows qw..qw+15) ----
        float sfr[8][4];
#pragma unroll
        for (int nf = 0; nf < 8; nf++)
#pragma unroll
            for (int j = 0; j < 4; j++) sfr[nf][j] = 0.f;
#pragma unroll
        for (int ks = 0; ks < 8; ks++) {
#pragma unroll
            for (int nf = 0; nf < 8; nf++) {
                uint2 b = *(const uint2*)&Kb[(nf * 8 + lq) * KS + ks * 8 + lr * 2];
                mma_f16(sfr[nf], qa[ks][0], qa[ks][1], qa[ks][2], qa[ks][3], b.x, b.y);
            }
        }

        // ---- masked static-shift softmax (no max, no rescale) ----
        const int q0 = qb + qw + lq, q1 = q0 + 8;
        const bool needmask = (s0 + 63) > (qb + qw);
        if (needmask) {
#pragma unroll
            for (int nf = 0; nf < 8; nf++) {
                int sA = s0 + nf * 8 + 2 * lr, sB = sA + 1;
                if (sA > q0) sfr[nf][0] = -1e30f;
                if (sB > q0) sfr[nf][1] = -1e30f;
                if (sA > q1) sfr[nf][2] = -1e30f;
                if (sB > q1) sfr[nf][3] = -1e30f;
            }
        }
        unsigned pu0[8], pu1[8];
#pragma unroll
        for (int nf = 0; nf < 8; nf++) {
            float p00 = fexp(sfr[nf][0] - CEXP);
            float p01 = fexp(sfr[nf][1] - CEXP);
            float p10 = fexp(sfr[nf][2] - CEXP);
            float p11 = fexp(sfr[nf][3] - CEXP);
            l0 += p00 + p01; l1 += p10 + p11;
            pu0[nf] = f2h2(p00, p01);
            pu1[nf] = f2h2(p10, p11);
        }

        // ---- O += P V : A = P (register-resident), B = V^T rows ------------
#pragma unroll
        for (int kk = 0; kk < 4; kk++) {
            unsigned a0 = pu0[2 * kk],     a1 = pu1[2 * kk];
            unsigned a2 = pu0[2 * kk + 1], a3 = pu1[2 * kk + 1];
#pragma unroll
            for (int nf = 0; nf < 16; nf++) {
                uint2 b = *(const uint2*)&Vb[(nf * 8 + lq) * VTS + kk * 8 + lr * 2];
                mma_f16(ofr[nf], a0, a1, a2, a3, b.x, b.y);
            }
        }
    }

    // ---- epilogue: quad-reduce sums, normalize, fp16-pack into Y -------------
    l0 += __shfl_xor_sync(0xffffffffu, l0, 1);
    l0 += __shfl_xor_sync(0xffffffffu, l0, 2);
    l1 += __shfl_xor_sync(0xffffffffu, l1, 1);
    l1 += __shfl_xor_sync(0xffffffffu, l1, 2);
    float inv0 = 1.0f / l0, inv1 = 1.0f / l1;
    unsigned* ya = Y + (size_t)(qb + qw + lq) * (D_MODEL / 2) + h * (HDIM / 2);
    unsigned* yb = ya + 8 * (size_t)(D_MODEL / 2);
#pragma unroll
    for (int nf = 0; nf < 16; nf++) {
        int off = (nf >> 1) * 8 + 2 * lr + (nf & 1);   // permuted word pos
        ya[off] = f2h2(ofr[nf][0] * inv0, ofr[nf][1] * inv0);
        yb[off] = f2h2(ofr[nf][2] * inv1, ofr[nf][3] * inv1);
    }
}

// ---------------- launch ------------------------------------------------------
extern "C" void kernel_launch(void* const* d_in, const int* in_sizes, int n_in,
                              void* d_out, int out_size) {
    const float* x        = (const float*)d_in[0];
    const float* ve       = (const float*)d_in[1];
    const float* qkv_w    = (const float*)d_in[2];
    const float* lambdas  = (const float*)d_in[3];
    const float* c_proj_w = (const float*)d_in[4];
    float* out = (float*)d_out;

    float* p_qkv;
    unsigned *p_q, *p_k, *p_v, *p_y, *p_xi, *p_wi, *p_cpi;
    cudaGetSymbolAddress((void**)&p_qkv, g_qkv);
    cudaGetSymbolAddress((void**)&p_q, g_q);
    cudaGetSymbolAddress((void**)&p_k, g_k);
    cudaGetSymbolAddress((void**)&p_v, g_v);
    cudaGetSymbolAddress((void**)&p_y, g_y);
    cudaGetSymbolAddress((void**)&p_xi, g_xi);
    cudaGetSymbolAddress((void**)&p_wi, g_wi);
    cudaGetSymbolAddress((void**)&p_cpi, g_cpi);

    static bool attr_set = false;
    if (!attr_set) {
        cudaFuncSetAttribute(gemm_h, cudaFuncAttributeMaxDynamicSharedMemorySize,
                             GEMM_SMEM);
        cudaFuncSetAttribute(attn_h, cudaFuncAttributeMaxDynamicSharedMemorySize,
                             ATTN_SMEM);
        attr_set = true;
    }

    // pre-pass conversions (fp32 -> permuted fp16 words)
    conv_h<<<1024, 256>>>(x, p_xi, T_LEN * D_MODEL / 16);
    conv_h<<<768, 256>>>(qkv_w, p_wi, 3 * D_MODEL * D_MODEL / 16);
    conv_h<<<256, 256>>>(c_proj_w, p_cpi, D_MODEL * D_MODEL / 16);

    // QKV projection
    gemm_h<<<dim3(3 * D_MODEL / 128, T_LEN / 128), 256, GEMM_SMEM>>>(
        p_xi, p_wi, p_qkv, T_LEN, 3 * D_MODEL, D_MODEL / 2);

    qkv_post<<<dim3(T_LEN / 2, NHEAD), 256>>>(p_qkv, ve, lambdas, p_q, p_k, p_v);

    attn_h<<<dim3(T_LEN / 128, NHEAD), 256, ATTN_SMEM>>>(p_q, p_k, p_v, p_y);

    // output projection
    gemm_h<<<dim3(D_MODEL / 128, T_LEN / 128), 256, GEMM_SMEM>>>(
        p_y, p_cpi, out, T_LEN, D_MODEL, D_MODEL / 2);
}

// round 14
// speedup vs baseline: 1.3327x; 1.0035x over previous
#include <cuda_runtime.h>
#include <cuda_fp16.h>
#include <cstdint>

#define T_LEN   4096
#define D_MODEL 1024
#define NHEAD   8
#define HDIM    128
#define ATTN_SCALE 0.12f
#define CEXP    5.9f   // static softmax shift: |s| <= 15.36, exp(15.6-5.9) < fp16 max

// ---------------- fp16 mma helpers -------------------------------------------
__device__ __forceinline__ void mma_f16(float* d,
    unsigned a0, unsigned a1, unsigned a2, unsigned a3,
    unsigned b0, unsigned b1) {
    asm volatile("mma.sync.aligned.m16n8k16.row.col.f32.f16.f16.f32 "
        "{%0,%1,%2,%3},{%4,%5,%6,%7},{%8,%9},{%0,%1,%2,%3};"
        : "+f"(d[0]), "+f"(d[1]), "+f"(d[2]), "+f"(d[3])
        : "r"(a0), "r"(a1), "r"(a2), "r"(a3), "r"(b0), "r"(b1));
}
// pack two f32 -> f16x2 word {lo, hi}. PTX: cvt d, a, b -> hi=a, lo=b.
__device__ __forceinline__ unsigned f2h2(float lo, float hi) {
    unsigned r;
    asm("cvt.rn.f16x2.f32 %0, %1, %2;" : "=r"(r) : "f"(hi), "f"(lo));
    return r;
}
// fast exp: 1 MUL + 1 MUFU.EX2 (large negative -> 0)
__device__ __forceinline__ float fexp(float x) { return __expf(x); }

__device__ __forceinline__ void cp16(void* smem_ptr, const void* gptr) {
    unsigned sa = (unsigned)__cvta_generic_to_shared(smem_ptr);
    asm volatile("cp.async.cg.shared.global [%0], [%1], 16;" :: "r"(sa), "l"(gptr));
}
#define CP_COMMIT() asm volatile("cp.async.commit_group;")
#define CP_WAIT(N)  asm volatile("cp.async.wait_group %0;" :: "n"(N))

// ---------------- scratch (word = fp16x2) -------------------------------------
__device__ float    g_qkv[(size_t)T_LEN * 3 * D_MODEL];          // fp32 gemm out
__device__ unsigned g_q[(size_t)NHEAD * T_LEN * (HDIM / 2)];     // fp16 words, perm, *scale
__device__ unsigned g_k[(size_t)NHEAD * T_LEN * (HDIM / 2)];     // fp16 words, perm
__device__ unsigned g_v[(size_t)NHEAD * HDIM * (T_LEN / 2)];     // V^T fp16 words, s-perm
__device__ unsigned g_y[(size_t)T_LEN * (D_MODEL / 2)];          // fp16 words, perm
__device__ unsigned g_xi[(size_t)T_LEN * (D_MODEL / 2)];
__device__ unsigned g_wi[(size_t)3 * D_MODEL * (D_MODEL / 2)];
__device__ unsigned g_cpi[(size_t)D_MODEL * (D_MODEL / 2)];

// ---------------- pre-pass: fp32 -> fp16 words, permuted within 16-elem groups
__global__ __launch_bounds__(256) void conv_h(const float* __restrict__ in,
                                              unsigned* __restrict__ out, int ng) {
    int g = blockIdx.x * 256 + threadIdx.x;
    if (g >= ng) return;
    const float4* ip = (const float4*)(in + (size_t)g * 16);
    float4 v0 = ip[0], v1 = ip[1], v2 = ip[2], v3 = ip[3];
    unsigned w0 = f2h2(v0.x, v0.y), w1 = f2h2(v0.z, v0.w);
    unsigned w2 = f2h2(v1.x, v1.y), w3 = f2h2(v1.z, v1.w);
    unsigned w4 = f2h2(v2.x, v2.y), w5 = f2h2(v2.z, v2.w);
    unsigned w6 = f2h2(v3.x, v3.y), w7 = f2h2(v3.z, v3.w);
    uint4 o0; o0.x = w0; o0.y = w4; o0.z = w1; o0.w = w5;
    uint4 o1; o1.x = w2; o1.y = w6; o1.z = w3; o1.w = w7;
    uint4* op = (uint4*)(out + (size_t)g * 8);
    op[0] = o0; op[1] = o1;
}

// ---------------- fp16 NT GEMM: C[M,N] = A[M,K] B[N,K]^T ----------------------
// 128 threads, 4 warps (2M x 2N), warp tile 64x64, BK=32 elems (16 words).
#define GST 20
#define GSTAGE (128 * GST)
#define GEMM_SMEM (4 * 2 * GSTAGE * 4)
__global__ __launch_bounds__(128, 2) void gemm_h(const unsigned* __restrict__ A,
                                                 const unsigned* __restrict__ B,
                                                 float* __restrict__ C,
                                                 int M, int N, int Kw) {
    extern __shared__ unsigned smu[];
    const int bm = blockIdx.y * 128, bn = blockIdx.x * 128;
    const int tid = threadIdx.x;
    const int wid = tid >> 5, lane = tid & 31;
    const int wm = (wid >> 1) * 64, wn = (wid & 1) * 64;
    const int lq = lane >> 2, lr = lane & 3;

    float acc[4][8][4];
#pragma unroll
    for (int mf = 0; mf < 4; mf++)
#pragma unroll
        for (int nf = 0; nf < 8; nf++)
#pragma unroll
            for (int j = 0; j < 4; j++) acc[mf][nf][j] = 0.f;

    const int nk = Kw >> 4;

    auto issue = [&](int it, int buf) {
        unsigned* sA = smu + buf * (2 * GSTAGE);
        unsigned* sB = sA + GSTAGE;
        int k0 = it << 4;
#pragma unroll
        for (int p = 0; p < 4; p++) {
            int e = tid + 128 * p;
            int r = e >> 2, ch = (e & 3) * 4;
            cp16(&sA[r * GST + ch], A + (size_t)(bm + r) * Kw + k0 + ch);
            cp16(&sB[r * GST + ch], B + (size_t)(bn + r) * Kw + k0 + ch);
        }
    };

    issue(0, 0); CP_COMMIT();
    issue(1, 1); CP_COMMIT();
    issue(2, 2); CP_COMMIT();

    for (int it = 0; it < nk; it++) {
        CP_WAIT(2);
        __syncthreads();
        if (it + 3 < nk) issue(it + 3, (it + 3) & 3);
        CP_COMMIT();

        const unsigned* sA = smu + (it & 3) * (2 * GSTAGE);
        const unsigned* sB = sA + GSTAGE;
#pragma unroll
        for (int ks = 0; ks < 2; ks++) {
            unsigned a[4][4];
#pragma unroll
            for (int mf = 0; mf < 4; mf++) {
                uint2 a02 = *(const uint2*)&sA[(wm + mf * 16 + lq) * GST + ks * 8 + lr * 2];
                uint2 a13 = *(const uint2*)&sA[(wm + mf * 16 + 8 + lq) * GST + ks * 8 + lr * 2];
                a[mf][0] = a02.x; a[mf][1] = a13.x; a[mf][2] = a02.y; a[mf][3] = a13.y;
            }
#pragma unroll
            for (int nf = 0; nf < 8; nf++) {
                uint2 b = *(const uint2*)&sB[(wn + nf * 8 + lq) * GST + ks * 8 + lr * 2];
#pragma unroll
                for (int mf = 0; mf < 4; mf++)
                    mma_f16(acc[mf][nf], a[mf][0], a[mf][1], a[mf][2], a[mf][3],
                            b.x, b.y);
            }
        }
    }
#pragma unroll
    for (int mf = 0; mf < 4; mf++)
#pragma unroll
        for (int nf = 0; nf < 8; nf++) {
            float* c0 = C + (size_t)(bm + wm + mf * 16 + lq) * N + bn + wn + nf * 8 + lr * 2;
            c0[0] = acc[mf][nf][0]; c0[1] = acc[mf][nf][1];
            float* c1 = c0 + 8 * (size_t)N;
            c1[0] = acc[mf][nf][2]; c1[1] = acc[mf][nf][3];
        }
}

// ---------------- RMSNorm + rotary + V blend (2 tokens/block) -----------------
__global__ __launch_bounds__(256) void qkv_post(const float* __restrict__ qkv,
                                                const float* __restrict__ ve,
                                                const float* __restrict__ lambdas,
                                                unsigned* __restrict__ Qw,
                                                unsigned* __restrict__ Kw,
                                                unsigned* __restrict__ Vtw) {
    const int sb = threadIdx.x >> 7;          // sub-block: token within pair
    const int d  = threadIdx.x & 127;
    const int t  = blockIdx.x * 2 + sb;
    const int h  = blockIdx.y;
    const int lane = d & 31, wid = d >> 5;
    const float* base = qkv + (size_t)t * (3 * D_MODEL) + h * HDIM;

    float qv = base[d];
    float kv = base[D_MODEL + d];
    float vv = base[2 * D_MODEL + d];

    float s1 = qv * qv, s2 = kv * kv;
#pragma unroll
    for (int o = 16; o; o >>= 1) {
        s1 += __shfl_xor_sync(0xffffffffu, s1, o);
        s2 += __shfl_xor_sync(0xffffffffu, s2, o);
    }
    __shared__ float w1[2][4], w2[2][4];
    if (lane == 0) { w1[sb][wid] = s1; w2[sb][wid] = s2; }
    __syncthreads();
    float sq = w1[sb][0] + w1[sb][1] + w1[sb][2] + w1[sb][3];
    float sk = w2[sb][0] + w2[sb][1] + w2[sb][2] + w2[sb][3];
    const float eps = 1.1920929e-7f;
    float rq = rsqrtf(sq * (1.0f / 128.0f) + eps);
    float rk = rsqrtf(sk * (1.0f / 128.0f) + eps);

    __shared__ float qs[2][128], ks[2][128];
    qs[sb][d] = qv * rq; ks[sb][d] = kv * rk;
    __syncthreads();

    int j = d & 63;
    float ang = (j < 32) ? exp2f((float)j * (-10.0f / 31.0f)) : 0.0f;
    float theta = (float)t * ang;
    float c, s;
    sincosf(theta, &s, &c);

    float qo, ko;
    if (d < 64) {
        qo =  qs[sb][d] * c + qs[sb][d + 64] * s;
        ko =  ks[sb][d] * c + ks[sb][d + 64] * s;
    } else {
        qo = -qs[sb][d - 64] * s + qs[sb][d] * c;
        ko = -ks[sb][d - 64] * s + ks[sb][d] * c;
    }

    float l0 = lambdas[0], l1 = lambdas[1];
    float vo = l0 * vv + l1 * ve[(size_t)t * D_MODEL + h * HDIM + d];

    // V^T [h][d][t], fp16, word-permuted along s within 16-s groups
    {
        int ws = t >> 1;
        int gg = ws >> 3, pp = ws & 7;
        int iw = (gg << 3) | (((pp & 3) << 1) | (pp >> 2));
        size_t widx = ((size_t)(h * HDIM + d)) * (T_LEN / 2) + iw;
        ((__half*)Vtw)[widx * 2 + (t & 1)] = __float2half_rn(vo);
    }

    __syncthreads();                 // rotary reads of qs/ks done
    qs[sb][d] = qo * ATTN_SCALE;
    ks[sb][d] = ko;
    __syncthreads();

    if (d < 64) {                    // pack word w=d (elems 2d, 2d+1), permuted
        int p = d & 7, g = d >> 3;
        int iw = (g << 3) | (((p & 3) << 1) | (p >> 2));
        size_t rbw = ((size_t)h * T_LEN + t) * (HDIM / 2);
        Qw[rbw + iw] = f2h2(qs[sb][2 * d], qs[sb][2 * d + 1]);
        Kw[rbw + iw] = f2h2(ks[sb][2 * d], ks[sb][2 * d + 1]);
    }
}

// ---------------- fp16 mma causal flash attention ------------------------------
// 256 thr, 8 warps, CTA = 128 q rows, 64-key tiles, double-buffered K & V^T.
// Static softmax shift: no online max, no rescale; sums reduced in epilogue.
#define KS  68                       // K tile row stride (64 words + 4)
#define KW  (64 * KS)
#define VTS 36                       // V^T tile row stride (32 words + 4)
#define VW  (128 * VTS)
#define ATTN_SMEM ((2 * KW + 2 * VW) * 4)
__global__ __launch_bounds__(256) void attn_h(const unsigned* __restrict__ Q,
                                              const unsigned* __restrict__ K,
                                              const unsigned* __restrict__ Vt,
                                              unsigned* __restrict__ Y) {
    extern __shared__ unsigned sm[];

    const int h  = blockIdx.y;
    const int qb = ((int)gridDim.x - 1 - (int)blockIdx.x) * 128;
    const int tid = threadIdx.x, wid = tid >> 5, lane = tid & 31;
    const int lq = lane >> 2, lr = lane & 3;
    const int qw = wid * 16;

    const unsigned* Khw = K + (size_t)h * T_LEN * (HDIM / 2);
    const unsigned* Vtwh = Vt + (size_t)h * HDIM * (T_LEN / 2);

    // persistent Q fragments: rows qb+qw+lq, +8 ; 8 k16-groups
    unsigned qa[8][4];
    {
        const unsigned* Qr0 = Q + ((size_t)h * T_LEN + qb + qw + lq) * (HDIM / 2);
        const unsigned* Qr1 = Qr0 + 8 * (HDIM / 2);
#pragma unroll
        for (int ks = 0; ks < 8; ks++) {
            uint2 a02 = *(const uint2*)&Qr0[ks * 8 + lr * 2];
            uint2 a13 = *(const uint2*)&Qr1[ks * 8 + lr * 2];
            qa[ks][0] = a02.x; qa[ks][1] = a13.x; qa[ks][2] = a02.y; qa[ks][3] = a13.y;
        }
    }

    float ofr[16][4];
#pragma unroll
    for (int nf = 0; nf < 16; nf++)
#pragma unroll
        for (int j = 0; j < 4; j++) ofr[nf][j] = 0.f;
    float l0 = 0.f, l1 = 0.f;        // per-thread partial sums (quad-reduced at end)

    const int ntiles = qb / 64 + 2;

    auto issue_kv = [&](int s0, int buf) {
        unsigned* Kb = sm + buf * KW;
        unsigned* Vb = sm + 2 * KW + buf * VW;
        const int s0w = s0 >> 1;
#pragma unroll
        for (int p = 0; p < 4; p++) {
            int e = tid + 256 * p;
            int rk = e >> 4, ck = (e & 15) * 4;
            cp16(&Kb[rk * KS + ck], Khw + (size_t)(s0 + rk) * (HDIM / 2) + ck);
            int rv = e >> 3, cv = (e & 7) * 4;
            cp16(&Vb[rv * VTS + cv], Vtwh + (size_t)rv * (T_LEN / 2) + s0w + cv);
        }
    };

    issue_kv(0, 0); CP_COMMIT();

    for (int it = 0; it < ntiles; it++) {
        const int s0 = it * 64;
        const int buf = it & 1;
        CP_WAIT(0);
        __syncthreads();                       // K,V (buf) visible; buf^1 free
        if (it + 1 < ntiles) issue_kv(s0 + 64, buf ^ 1);
        CP_COMMIT();

        const unsigned* Kb = sm + buf * KW;
        const unsigned* Vb = sm + 2 * KW + buf * VW;

        // ---- S = Q K^T (warp rows qw..qw+15) ----
        float sfr[8][4];
#pragma unroll
        for (int nf = 0; nf < 8; nf++)
#pragma unroll
            for (int j = 0; j < 4; j++) sfr[nf][j] = 0.f;
#pragma unroll
        for (int ks = 0; ks < 8; ks++) {
#pragma unroll
            for (int nf = 0; nf < 8; nf++) {
                uint2 b = *(const uint2*)&Kb[(nf * 8 + lq) * KS + ks * 8 + lr * 2];
                mma_f16(sfr[nf], qa[ks][0], qa[ks][1], qa[ks][2], qa[ks][3], b.x, b.y);
            }
        }

        // ---- masked static-shift softmax (no max, no rescale) ----
        const int q0 = qb + qw + lq, q1 = q0 + 8;
        const bool needmask = (s0 + 63) > (qb + qw);
        if (needmask) {
#pragma unroll
            for (int nf = 0; nf < 8; nf++) {
                int sA = s0 + nf * 8 + 2 * lr, sB = sA + 1;
                if (sA > q0) sfr[nf][0] = -1e30f;
                if (sB > q0) sfr[nf][1] = -1e30f;
                if (sA > q1) sfr[nf][2] = -1e30f;
                if (sB > q1) sfr[nf][3] = -1e30f;
            }
        }
        unsigned pu0[8], pu1[8];
#pragma unroll
        for (int nf = 0; nf < 8; nf++) {
            float p00 = fexp(sfr[nf][0] - CEXP);
            float p01 = fexp(sfr[nf][1] - CEXP);
            float p10 = fexp(sfr[nf][2] - CEXP);
            float p11 = fexp(sfr[nf][3] - CEXP);
            l0 += p00 + p01; l1 += p10 + p11;
            pu0[nf] = f2h2(p00, p01);
            pu1[nf] = f2h2(p10, p11);
        }

        // ---- O += P V : A = P (register-resident), B = V^T rows ------------
#pragma unroll
        for (int kk = 0; kk < 4; kk++) {
            unsigned a0 = pu0[2 * kk],     a1 = pu1[2 * kk];
            unsigned a2 = pu0[2 * kk + 1], a3 = pu1[2 * kk + 1];
#pragma unroll
            for (int nf = 0; nf < 16; nf++) {
                uint2 b = *(const uint2*)&Vb[(nf * 8 + lq) * VTS + kk * 8 + lr * 2];
                mma_f16(ofr[nf], a0, a1, a2, a3, b.x, b.y);
            }
        }
    }

    // ---- epilogue: quad-reduce sums, normalize, fp16-pack into Y -------------
    l0 += __shfl_xor_sync(0xffffffffu, l0, 1);
    l0 += __shfl_xor_sync(0xffffffffu, l0, 2);
    l1 += __shfl_xor_sync(0xffffffffu, l1, 1);
    l1 += __shfl_xor_sync(0xffffffffu, l1, 2);
    float inv0 = 1.0f / l0, inv1 = 1.0f / l1;
    unsigned* ya = Y + (size_t)(qb + qw + lq) * (D_MODEL / 2) + h * (HDIM / 2);
    unsigned* yb = ya + 8 * (size_t)(D_MODEL / 2);
#pragma unroll
    for (int nf = 0; nf < 16; nf++) {
        int off = (nf >> 1) * 8 + 2 * lr + (nf & 1);   // permuted word pos
        ya[off] = f2h2(ofr[nf][0] * inv0, ofr[nf][1] * inv0);
        yb[off] = f2h2(ofr[nf][2] * inv1, ofr[nf][3] * inv1);
    }
}

// ---------------- launch ------------------------------------------------------
extern "C" void kernel_launch(void* const* d_in, const int* in_sizes, int n_in,
                              void* d_out, int out_size) {
    const float* x        = (const float*)d_in[0];
    const float* ve       = (const float*)d_in[1];
    const float* qkv_w    = (const float*)d_in[2];
    const float* lambdas  = (const float*)d_in[3];
    const float* c_proj_w = (const float*)d_in[4];
    float* out = (float*)d_out;

    float* p_qkv;
    unsigned *p_q, *p_k, *p_v, *p_y, *p_xi, *p_wi, *p_cpi;
    cudaGetSymbolAddress((void**)&p_qkv, g_qkv);
    cudaGetSymbolAddress((void**)&p_q, g_q);
    cudaGetSymbolAddress((void**)&p_k, g_k);
    cudaGetSymbolAddress((void**)&p_v, g_v);
    cudaGetSymbolAddress((void**)&p_y, g_y);
    cudaGetSymbolAddress((void**)&p_xi, g_xi);
    cudaGetSymbolAddress((void**)&p_wi, g_wi);
    cudaGetSymbolAddress((void**)&p_cpi, g_cpi);

    static bool attr_set = false;
    if (!attr_set) {
        cudaFuncSetAttribute(gemm_h, cudaFuncAttributeMaxDynamicSharedMemorySize,
                             GEMM_SMEM);
        cudaFuncSetAttribute(attn_h, cudaFuncAttributeMaxDynamicSharedMemorySize,
                             ATTN_SMEM);
        attr_set = true;
    }

    // pre-pass conversions (fp32 -> permuted fp16 words)
    conv_h<<<1024, 256>>>(x, p_xi, T_LEN * D_MODEL / 16);
    conv_h<<<768, 256>>>(qkv_w, p_wi, 3 * D_MODEL * D_MODEL / 16);
    conv_h<<<256, 256>>>(c_proj_w, p_cpi, D_MODEL * D_MODEL / 16);

    // QKV projection
    gemm_h<<<dim3(3 * D_MODEL / 128, T_LEN / 128), 128, GEMM_SMEM>>>(
        p_xi, p_wi, p_qkv, T_LEN, 3 * D_MODEL, D_MODEL / 2);

    qkv_post<<<dim3(T_LEN / 2, NHEAD), 256>>>(p_qkv, ve, lambdas, p_q, p_k, p_v);

    attn_h<<<dim3(T_LEN / 128, NHEAD), 256, ATTN_SMEM>>>(p_q, p_k, p_v, p_y);

    // output projection
    gemm_h<<<dim3(D_MODEL / 128, T_LEN / 128), 128, GEMM_SMEM>>>(
        p_y, p_cpi, out, T_LEN, D_MODEL, D_MODEL / 2);
}

// round 15
// speedup vs baseline: 1.4633x; 1.0981x over previous
#include <cuda_runtime.h>
#include <cuda_fp16.h>
#include <cstdint>

#define T_LEN   4096
#define D_MODEL 1024
#define NHEAD   8
#define HDIM    128
#define ATTN_SCALE 0.12f
#define CEXP    5.9f   // static softmax shift: |s| <= 15.36, exp(15.6-5.9) < fp16 max

// ---------------- fp16 mma helpers -------------------------------------------
__device__ __forceinline__ void mma_f16(float* d,
    unsigned a0, unsigned a1, unsigned a2, unsigned a3,
    unsigned b0, unsigned b1) {
    asm volatile("mma.sync.aligned.m16n8k16.row.col.f32.f16.f16.f32 "
        "{%0,%1,%2,%3},{%4,%5,%6,%7},{%8,%9},{%0,%1,%2,%3};"
        : "+f"(d[0]), "+f"(d[1]), "+f"(d[2]), "+f"(d[3])
        : "r"(a0), "r"(a1), "r"(a2), "r"(a3), "r"(b0), "r"(b1));
}
// pack two f32 -> f16x2 word {lo, hi}. PTX: cvt d, a, b -> hi=a, lo=b.
__device__ __forceinline__ unsigned f2h2(float lo, float hi) {
    unsigned r;
    asm("cvt.rn.f16x2.f32 %0, %1, %2;" : "=r"(r) : "f"(hi), "f"(lo));
    return r;
}
// fast exp: 1 MUL + 1 MUFU.EX2 (large negative -> 0)
__device__ __forceinline__ float fexp(float x) { return __expf(x); }

__device__ __forceinline__ void cp16(void* smem_ptr, const void* gptr) {
    unsigned sa = (unsigned)__cvta_generic_to_shared(smem_ptr);
    asm volatile("cp.async.cg.shared.global [%0], [%1], 16;" :: "r"(sa), "l"(gptr));
}
#define CP_COMMIT() asm volatile("cp.async.commit_group;")
#define CP_WAIT(N)  asm volatile("cp.async.wait_group %0;" :: "n"(N))

// ---------------- scratch (word = fp16x2) -------------------------------------
__device__ float    g_qkv[(size_t)T_LEN * 3 * D_MODEL];          // fp32 gemm out
__device__ unsigned g_q[(size_t)NHEAD * T_LEN * (HDIM / 2)];     // fp16 words, perm, *scale
__device__ unsigned g_k[(size_t)NHEAD * T_LEN * (HDIM / 2)];     // fp16 words, perm
__device__ unsigned g_v[(size_t)NHEAD * HDIM * (T_LEN / 2)];     // V^T fp16 words, s-perm
__device__ unsigned g_y[(size_t)T_LEN * (D_MODEL / 2)];          // fp16 words, perm
__device__ unsigned g_xi[(size_t)T_LEN * (D_MODEL / 2)];
__device__ unsigned g_wi[(size_t)3 * D_MODEL * (D_MODEL / 2)];
__device__ unsigned g_cpi[(size_t)D_MODEL * (D_MODEL / 2)];

// ---------------- pre-pass: fp32 -> fp16 words, permuted within 16-elem groups
__global__ __launch_bounds__(256) void conv_h(const float* __restrict__ in,
                                              unsigned* __restrict__ out, int ng) {
    int g = blockIdx.x * 256 + threadIdx.x;
    if (g >= ng) return;
    const float4* ip = (const float4*)(in + (size_t)g * 16);
    float4 v0 = ip[0], v1 = ip[1], v2 = ip[2], v3 = ip[3];
    unsigned w0 = f2h2(v0.x, v0.y), w1 = f2h2(v0.z, v0.w);
    unsigned w2 = f2h2(v1.x, v1.y), w3 = f2h2(v1.z, v1.w);
    unsigned w4 = f2h2(v2.x, v2.y), w5 = f2h2(v2.z, v2.w);
    unsigned w6 = f2h2(v3.x, v3.y), w7 = f2h2(v3.z, v3.w);
    uint4 o0; o0.x = w0; o0.y = w4; o0.z = w1; o0.w = w5;
    uint4 o1; o1.x = w2; o1.y = w6; o1.z = w3; o1.w = w7;
    uint4* op = (uint4*)(out + (size_t)g * 8);
    op[0] = o0; op[1] = o1;
}

// ---------------- fp16 NT GEMM: C[M,N] = A[M,K] B[N,K]^T ----------------------
// 128 threads, 4 warps (2M x 2N), warp tile 64x64, BK=32 elems (16 words).
#define GST 20
#define GSTAGE (128 * GST)
#define GEMM_SMEM (4 * 2 * GSTAGE * 4)
__global__ __launch_bounds__(128, 2) void gemm_h(const unsigned* __restrict__ A,
                                                 const unsigned* __restrict__ B,
                                                 float* __restrict__ C,
                                                 int M, int N, int Kw) {
    extern __shared__ unsigned smu[];
    const int bm = blockIdx.y * 128, bn = blockIdx.x * 128;
    const int tid = threadIdx.x;
    const int wid = tid >> 5, lane = tid & 31;
    const int wm = (wid >> 1) * 64, wn = (wid & 1) * 64;
    const int lq = lane >> 2, lr = lane & 3;

    float acc[4][8][4];
#pragma unroll
    for (int mf = 0; mf < 4; mf++)
#pragma unroll
        for (int nf = 0; nf < 8; nf++)
#pragma unroll
            for (int j = 0; j < 4; j++) acc[mf][nf][j] = 0.f;

    const int nk = Kw >> 4;

    auto issue = [&](int it, int buf) {
        unsigned* sA = smu + buf * (2 * GSTAGE);
        unsigned* sB = sA + GSTAGE;
        int k0 = it << 4;
#pragma unroll
        for (int p = 0; p < 4; p++) {
            int e = tid + 128 * p;
            int r = e >> 2, ch = (e & 3) * 4;
            cp16(&sA[r * GST + ch], A + (size_t)(bm + r) * Kw + k0 + ch);
            cp16(&sB[r * GST + ch], B + (size_t)(bn + r) * Kw + k0 + ch);
        }
    };

    issue(0, 0); CP_COMMIT();
    issue(1, 1); CP_COMMIT();
    issue(2, 2); CP_COMMIT();

    for (int it = 0; it < nk; it++) {
        CP_WAIT(2);
        __syncthreads();
        if (it + 3 < nk) issue(it + 3, (it + 3) & 3);
        CP_COMMIT();

        const unsigned* sA = smu + (it & 3) * (2 * GSTAGE);
        const unsigned* sB = sA + GSTAGE;
#pragma unroll
        for (int ks = 0; ks < 2; ks++) {
            unsigned a[4][4];
#pragma unroll
            for (int mf = 0; mf < 4; mf++) {
                uint2 a02 = *(const uint2*)&sA[(wm + mf * 16 + lq) * GST + ks * 8 + lr * 2];
                uint2 a13 = *(const uint2*)&sA[(wm + mf * 16 + 8 + lq) * GST + ks * 8 + lr * 2];
                a[mf][0] = a02.x; a[mf][1] = a13.x; a[mf][2] = a02.y; a[mf][3] = a13.y;
            }
#pragma unroll
            for (int nf = 0; nf < 8; nf++) {
                uint2 b = *(const uint2*)&sB[(wn + nf * 8 + lq) * GST + ks * 8 + lr * 2];
#pragma unroll
                for (int mf = 0; mf < 4; mf++)
                    mma_f16(acc[mf][nf], a[mf][0], a[mf][1], a[mf][2], a[mf][3],
                            b.x, b.y);
            }
        }
    }
#pragma unroll
    for (int mf = 0; mf < 4; mf++)
#pragma unroll
        for (int nf = 0; nf < 8; nf++) {
            float* c0 = C + (size_t)(bm + wm + mf * 16 + lq) * N + bn + wn + nf * 8 + lr * 2;
            c0[0] = acc[mf][nf][0]; c0[1] = acc[mf][nf][1];
            float* c1 = c0 + 8 * (size_t)N;
            c1[0] = acc[mf][nf][2]; c1[1] = acc[mf][nf][3];
        }
}

// ---------------- RMSNorm + rotary + V blend (2 tokens/block) -----------------
__global__ __launch_bounds__(256) void qkv_post(const float* __restrict__ qkv,
                                                const float* __restrict__ ve,
                                                const float* __restrict__ lambdas,
                                                unsigned* __restrict__ Qw,
                                                unsigned* __restrict__ Kw,
                                                unsigned* __restrict__ Vtw) {
    const int sb = threadIdx.x >> 7;          // sub-block: token within pair
    const int d  = threadIdx.x & 127;
    const int t  = blockIdx.x * 2 + sb;
    const int h  = blockIdx.y;
    const int lane = d & 31, wid = d >> 5;
    const float* base = qkv + (size_t)t * (3 * D_MODEL) + h * HDIM;

    float qv = base[d];
    float kv = base[D_MODEL + d];
    float vv = base[2 * D_MODEL + d];

    float s1 = qv * qv, s2 = kv * kv;
#pragma unroll
    for (int o = 16; o; o >>= 1) {
        s1 += __shfl_xor_sync(0xffffffffu, s1, o);
        s2 += __shfl_xor_sync(0xffffffffu, s2, o);
    }
    __shared__ float w1[2][4], w2[2][4];
    if (lane == 0) { w1[sb][wid] = s1; w2[sb][wid] = s2; }
    __syncthreads();
    float sq = w1[sb][0] + w1[sb][1] + w1[sb][2] + w1[sb][3];
    float sk = w2[sb][0] + w2[sb][1] + w2[sb][2] + w2[sb][3];
    const float eps = 1.1920929e-7f;
    float rq = rsqrtf(sq * (1.0f / 128.0f) + eps);
    float rk = rsqrtf(sk * (1.0f / 128.0f) + eps);

    __shared__ float qs[2][128], ks[2][128];
    qs[sb][d] = qv * rq; ks[sb][d] = kv * rk;
    __syncthreads();

    int j = d & 63;
    float ang = (j < 32) ? exp2f((float)j * (-10.0f / 31.0f)) : 0.0f;
    float theta = (float)t * ang;
    float c, s;
    sincosf(theta, &s, &c);

    float qo, ko;
    if (d < 64) {
        qo =  qs[sb][d] * c + qs[sb][d + 64] * s;
        ko =  ks[sb][d] * c + ks[sb][d + 64] * s;
    } else {
        qo = -qs[sb][d - 64] * s + qs[sb][d] * c;
        ko = -ks[sb][d - 64] * s + ks[sb][d] * c;
    }

    float l0 = lambdas[0], l1 = lambdas[1];
    float vo = l0 * vv + l1 * ve[(size_t)t * D_MODEL + h * HDIM + d];

    // V^T [h][d][t], fp16, word-permuted along s within 16-s groups
    {
        int ws = t >> 1;
        int gg = ws >> 3, pp = ws & 7;
        int iw = (gg << 3) | (((pp & 3) << 1) | (pp >> 2));
        size_t widx = ((size_t)(h * HDIM + d)) * (T_LEN / 2) + iw;
        ((__half*)Vtw)[widx * 2 + (t & 1)] = __float2half_rn(vo);
    }

    __syncthreads();                 // rotary reads of qs/ks done
    qs[sb][d] = qo * ATTN_SCALE;
    ks[sb][d] = ko;
    __syncthreads();

    if (d < 64) {                    // pack word w=d (elems 2d, 2d+1), permuted
        int p = d & 7, g = d >> 3;
        int iw = (g << 3) | (((p & 3) << 1) | (p >> 2));
        size_t rbw = ((size_t)h * T_LEN + t) * (HDIM / 2);
        Qw[rbw + iw] = f2h2(qs[sb][2 * d], qs[sb][2 * d + 1]);
        Kw[rbw + iw] = f2h2(ks[sb][2 * d], ks[sb][2 * d + 1]);
    }
}

// ---------------- fp16 mma causal flash attention (2 CTAs/SM) ------------------
// 128 thr, 4 warps, CTA = 64 q rows, 64-key tiles, double-buffered K & V^T.
// Static softmax shift; Q frags persistent in registers; P register-resident.
#define KS  68                       // K tile row stride (64 words + 4)
#define KW  (64 * KS)
#define VTS 36                       // V^T tile row stride (32 words + 4)
#define VW  (128 * VTS)
#define ATTN_SMEM ((2 * KW + 2 * VW) * 4)
__global__ __launch_bounds__(128, 2) void attn_h(const unsigned* __restrict__ Q,
                                                 const unsigned* __restrict__ K,
                                                 const unsigned* __restrict__ Vt,
                                                 unsigned* __restrict__ Y) {
    extern __shared__ unsigned sm[];

    const int h  = blockIdx.y;
    const int qb = ((int)gridDim.x - 1 - (int)blockIdx.x) * 64;
    const int tid = threadIdx.x, wid = tid >> 5, lane = tid & 31;
    const int lq = lane >> 2, lr = lane & 3;
    const int qw = wid * 16;

    const unsigned* Khw = K + (size_t)h * T_LEN * (HDIM / 2);
    const unsigned* Vtwh = Vt + (size_t)h * HDIM * (T_LEN / 2);

    // persistent Q fragments: rows qb+qw+lq, +8 ; 8 k16-groups
    unsigned qa[8][4];
    {
        const unsigned* Qr0 = Q + ((size_t)h * T_LEN + qb + qw + lq) * (HDIM / 2);
        const unsigned* Qr1 = Qr0 + 8 * (HDIM / 2);
#pragma unroll
        for (int ks = 0; ks < 8; ks++) {
            uint2 a02 = *(const uint2*)&Qr0[ks * 8 + lr * 2];
            uint2 a13 = *(const uint2*)&Qr1[ks * 8 + lr * 2];
            qa[ks][0] = a02.x; qa[ks][1] = a13.x; qa[ks][2] = a02.y; qa[ks][3] = a13.y;
        }
    }

    float ofr[16][4];
#pragma unroll
    for (int nf = 0; nf < 16; nf++)
#pragma unroll
        for (int j = 0; j < 4; j++) ofr[nf][j] = 0.f;
    float l0 = 0.f, l1 = 0.f;        // per-thread partial sums (quad-reduced at end)

    const int ntiles = qb / 64 + 1;

    auto issue_kv = [&](int s0, int buf) {
        unsigned* Kb = sm + buf * KW;
        unsigned* Vb = sm + 2 * KW + buf * VW;
        const int s0w = s0 >> 1;
#pragma unroll
        for (int p = 0; p < 8; p++) {
            int e = tid + 128 * p;
            int rk = e >> 4, ck = (e & 15) * 4;
            cp16(&Kb[rk * KS + ck], Khw + (size_t)(s0 + rk) * (HDIM / 2) + ck);
            int rv = e >> 3, cv = (e & 7) * 4;
            cp16(&Vb[rv * VTS + cv], Vtwh + (size_t)rv * (T_LEN / 2) + s0w + cv);
        }
    };

    issue_kv(0, 0); CP_COMMIT();

    for (int it = 0; it < ntiles; it++) {
        const int s0 = it * 64;
        const int buf = it & 1;
        CP_WAIT(0);
        __syncthreads();                       // K,V (buf) visible; buf^1 free
        if (it + 1 < ntiles) issue_kv(s0 + 64, buf ^ 1);
        CP_COMMIT();

        const unsigned* Kb = sm + buf * KW;
        const unsigned* Vb = sm + 2 * KW + buf * VW;

        // ---- S = Q K^T (warp rows qw..qw+15) ----
        float sfr[8][4];
#pragma unroll
        for (int nf = 0; nf < 8; nf++)
#pragma unroll
            for (int j = 0; j < 4; j++) sfr[nf][j] = 0.f;
#pragma unroll
        for (int ks = 0; ks < 8; ks++) {
#pragma unroll
            for (int nf = 0; nf < 8; nf++) {
                uint2 b = *(const uint2*)&Kb[(nf * 8 + lq) * KS + ks * 8 + lr * 2];
                mma_f16(sfr[nf], qa[ks][0], qa[ks][1], qa[ks][2], qa[ks][3], b.x, b.y);
            }
        }

        // ---- masked static-shift softmax (no max, no rescale) ----
        const int q0 = qb + qw + lq, q1 = q0 + 8;
        const bool needmask = (s0 + 63) > (qb + qw);
        if (needmask) {
#pragma unroll
            for (int nf = 0; nf < 8; nf++) {
                int sA = s0 + nf * 8 + 2 * lr, sB = sA + 1;
                if (sA > q0) sfr[nf][0] = -1e30f;
                if (sB > q0) sfr[nf][1] = -1e30f;
                if (sA > q1) sfr[nf][2] = -1e30f;
                if (sB > q1) sfr[nf][3] = -1e30f;
            }
        }
        unsigned pu0[8], pu1[8];
#pragma unroll
        for (int nf = 0; nf < 8; nf++) {
            float p00 = fexp(sfr[nf][0] - CEXP);
            float p01 = fexp(sfr[nf][1] - CEXP);
            float p10 = fexp(sfr[nf][2] - CEXP);
            float p11 = fexp(sfr[nf][3] - CEXP);
            l0 += p00 + p01; l1 += p10 + p11;
            pu0[nf] = f2h2(p00, p01);
            pu1[nf] = f2h2(p10, p11);
        }

        // ---- O += P V : A = P (register-resident), B = V^T rows ------------
#pragma unroll
        for (int kk = 0; kk < 4; kk++) {
            unsigned a0 = pu0[2 * kk],     a1 = pu1[2 * kk];
            unsigned a2 = pu0[2 * kk + 1], a3 = pu1[2 * kk + 1];
#pragma unroll
            for (int nf = 0; nf < 16; nf++) {
                uint2 b = *(const uint2*)&Vb[(nf * 8 + lq) * VTS + kk * 8 + lr * 2];
                mma_f16(ofr[nf], a0, a1, a2, a3, b.x, b.y);
            }
        }
    }

    // ---- epilogue: quad-reduce sums, normalize, fp16-pack into Y -------------
    l0 += __shfl_xor_sync(0xffffffffu, l0, 1);
    l0 += __shfl_xor_sync(0xffffffffu, l0, 2);
    l1 += __shfl_xor_sync(0xffffffffu, l1, 1);
    l1 += __shfl_xor_sync(0xffffffffu, l1, 2);
    float inv0 = 1.0f / l0, inv1 = 1.0f / l1;
    unsigned* ya = Y + (size_t)(qb + qw + lq) * (D_MODEL / 2) + h * (HDIM / 2);
    unsigned* yb = ya + 8 * (size_t)(D_MODEL / 2);
#pragma unroll
    for (int nf = 0; nf < 16; nf++) {
        int off = (nf >> 1) * 8 + 2 * lr + (nf & 1);   // permuted word pos
        ya[off] = f2h2(ofr[nf][0] * inv0, ofr[nf][1] * inv0);
        yb[off] = f2h2(ofr[nf][2] * inv1, ofr[nf][3] * inv1);
    }
}

// ---------------- launch ------------------------------------------------------
extern "C" void kernel_launch(void* const* d_in, const int* in_sizes, int n_in,
                              void* d_out, int out_size) {
    const float* x        = (const float*)d_in[0];
    const float* ve       = (const float*)d_in[1];
    const float* qkv_w    = (const float*)d_in[2];
    const float* lambdas  = (const float*)d_in[3];
    const float* c_proj_w = (const float*)d_in[4];
    float* out = (float*)d_out;

    float* p_qkv;
    unsigned *p_q, *p_k, *p_v, *p_y, *p_xi, *p_wi, *p_cpi;
    cudaGetSymbolAddress((void**)&p_qkv, g_qkv);
    cudaGetSymbolAddress((void**)&p_q, g_q);
    cudaGetSymbolAddress((void**)&p_k, g_k);
    cudaGetSymbolAddress((void**)&p_v, g_v);
    cudaGetSymbolAddress((void**)&p_y, g_y);
    cudaGetSymbolAddress((void**)&p_xi, g_xi);
    cudaGetSymbolAddress((void**)&p_wi, g_wi);
    cudaGetSymbolAddress((void**)&p_cpi, g_cpi);

    static bool attr_set = false;
    if (!attr_set) {
        cudaFuncSetAttribute(gemm_h, cudaFuncAttributeMaxDynamicSharedMemorySize,
                             GEMM_SMEM);
        cudaFuncSetAttribute(attn_h, cudaFuncAttributeMaxDynamicSharedMemorySize,
                             ATTN_SMEM);
        attr_set = true;
    }

    // pre-pass conversions (fp32 -> permuted fp16 words)
    conv_h<<<1024, 256>>>(x, p_xi, T_LEN * D_MODEL / 16);
    conv_h<<<768, 256>>>(qkv_w, p_wi, 3 * D_MODEL * D_MODEL / 16);
    conv_h<<<256, 256>>>(c_proj_w, p_cpi, D_MODEL * D_MODEL / 16);

    // QKV projection
    gemm_h<<<dim3(3 * D_MODEL / 128, T_LEN / 128), 128, GEMM_SMEM>>>(
        p_xi, p_wi, p_qkv, T_LEN, 3 * D_MODEL, D_MODEL / 2);

    qkv_post<<<dim3(T_LEN / 2, NHEAD), 256>>>(p_qkv, ve, lambdas, p_q, p_k, p_v);

    attn_h<<<dim3(T_LEN / 64, NHEAD), 128, ATTN_SMEM>>>(p_q, p_k, p_v, p_y);

    // output projection
    gemm_h<<<dim3(D_MODEL / 128, T_LEN / 128), 128, GEMM_SMEM>>>(
        p_y, p_cpi, out, T_LEN, D_MODEL, D_MODEL / 2);
}

// round 16
// speedup vs baseline: 1.5271x; 1.0435x over previous
#include <cuda_runtime.h>
#include <cuda_fp16.h>
#include <cstdint>

#define T_LEN   4096
#define D_MODEL 1024
#define NHEAD   8
#define HDIM    128
#define ATTN_SCALE 0.12f
#define CEXP    5.9f   // static softmax shift: |s| <= 15.36, exp(15.6-5.9) < fp16 max

// ---------------- fp16 mma helpers -------------------------------------------
__device__ __forceinline__ void mma_f16(float* d,
    unsigned a0, unsigned a1, unsigned a2, unsigned a3,
    unsigned b0, unsigned b1) {
    asm volatile("mma.sync.aligned.m16n8k16.row.col.f32.f16.f16.f32 "
        "{%0,%1,%2,%3},{%4,%5,%6,%7},{%8,%9},{%0,%1,%2,%3};"
        : "+f"(d[0]), "+f"(d[1]), "+f"(d[2]), "+f"(d[3])
        : "r"(a0), "r"(a1), "r"(a2), "r"(a3), "r"(b0), "r"(b1));
}
// pack two f32 -> f16x2 word {lo, hi}. PTX: cvt d, a, b -> hi=a, lo=b.
__device__ __forceinline__ unsigned f2h2(float lo, float hi) {
    unsigned r;
    asm("cvt.rn.f16x2.f32 %0, %1, %2;" : "=r"(r) : "f"(hi), "f"(lo));
    return r;
}
// fast exp: 1 MUL + 1 MUFU.EX2 (large negative -> 0)
__device__ __forceinline__ float fexp(float x) { return __expf(x); }

__device__ __forceinline__ void cp16(void* smem_ptr, const void* gptr) {
    unsigned sa = (unsigned)__cvta_generic_to_shared(smem_ptr);
    asm volatile("cp.async.cg.shared.global [%0], [%1], 16;" :: "r"(sa), "l"(gptr));
}
#define CP_COMMIT() asm volatile("cp.async.commit_group;")
#define CP_WAIT(N)  asm volatile("cp.async.wait_group %0;" :: "n"(N))

// ---------------- scratch (word = fp16x2) -------------------------------------
__device__ float    g_qkv[(size_t)T_LEN * 3 * D_MODEL];          // fp32 gemm out
__device__ unsigned g_q[(size_t)NHEAD * T_LEN * (HDIM / 2)];     // fp16 words, perm, *scale
__device__ unsigned g_k[(size_t)NHEAD * T_LEN * (HDIM / 2)];     // fp16 words, perm
__device__ unsigned g_v[(size_t)NHEAD * HDIM * (T_LEN / 2)];     // V^T fp16 words, s-perm
__device__ unsigned g_y[(size_t)T_LEN * (D_MODEL / 2)];          // fp16 words, perm
__device__ unsigned g_xi[(size_t)T_LEN * (D_MODEL / 2)];
__device__ unsigned g_wi[(size_t)3 * D_MODEL * (D_MODEL / 2)];
__device__ unsigned g_cpi[(size_t)D_MODEL * (D_MODEL / 2)];
__device__ float    g_po[(size_t)2 * T_LEN * D_MODEL];           // split-K partial O
__device__ float    g_pl[2 * NHEAD * T_LEN];                     // split-K partial l

// ---------------- pre-pass: fp32 -> fp16 words, permuted within 16-elem groups
__global__ __launch_bounds__(256) void conv_h(const float* __restrict__ in,
                                              unsigned* __restrict__ out, int ng) {
    int g = blockIdx.x * 256 + threadIdx.x;
    if (g >= ng) return;
    const float4* ip = (const float4*)(in + (size_t)g * 16);
    float4 v0 = ip[0], v1 = ip[1], v2 = ip[2], v3 = ip[3];
    unsigned w0 = f2h2(v0.x, v0.y), w1 = f2h2(v0.z, v0.w);
    unsigned w2 = f2h2(v1.x, v1.y), w3 = f2h2(v1.z, v1.w);
    unsigned w4 = f2h2(v2.x, v2.y), w5 = f2h2(v2.z, v2.w);
    unsigned w6 = f2h2(v3.x, v3.y), w7 = f2h2(v3.z, v3.w);
    uint4 o0; o0.x = w0; o0.y = w4; o0.z = w1; o0.w = w5;
    uint4 o1; o1.x = w2; o1.y = w6; o1.z = w3; o1.w = w7;
    uint4* op = (uint4*)(out + (size_t)g * 8);
    op[0] = o0; op[1] = o1;
}

// ---------------- fp16 NT GEMM: C[M,N] = A[M,K] B[N,K]^T ----------------------
// 128 threads, 4 warps (2M x 2N), warp tile 64x64, BK=32 elems (16 words).
#define GST 20
#define GSTAGE (128 * GST)
#define GEMM_SMEM (4 * 2 * GSTAGE * 4)
__global__ __launch_bounds__(128, 2) void gemm_h(const unsigned* __restrict__ A,
                                                 const unsigned* __restrict__ B,
                                                 float* __restrict__ C,
                                                 int M, int N, int Kw) {
    extern __shared__ unsigned smu[];
    const int bm = blockIdx.y * 128, bn = blockIdx.x * 128;
    const int tid = threadIdx.x;
    const int wid = tid >> 5, lane = tid & 31;
    const int wm = (wid >> 1) * 64, wn = (wid & 1) * 64;
    const int lq = lane >> 2, lr = lane & 3;

    float acc[4][8][4];
#pragma unroll
    for (int mf = 0; mf < 4; mf++)
#pragma unroll
        for (int nf = 0; nf < 8; nf++)
#pragma unroll
            for (int j = 0; j < 4; j++) acc[mf][nf][j] = 0.f;

    const int nk = Kw >> 4;

    auto issue = [&](int it, int buf) {
        unsigned* sA = smu + buf * (2 * GSTAGE);
        unsigned* sB = sA + GSTAGE;
        int k0 = it << 4;
#pragma unroll
        for (int p = 0; p < 4; p++) {
            int e = tid + 128 * p;
            int r = e >> 2, ch = (e & 3) * 4;
            cp16(&sA[r * GST + ch], A + (size_t)(bm + r) * Kw + k0 + ch);
            cp16(&sB[r * GST + ch], B + (size_t)(bn + r) * Kw + k0 + ch);
        }
    };

    issue(0, 0); CP_COMMIT();
    issue(1, 1); CP_COMMIT();
    issue(2, 2); CP_COMMIT();

    for (int it = 0; it < nk; it++) {
        CP_WAIT(2);
        __syncthreads();
        if (it + 3 < nk) issue(it + 3, (it + 3) & 3);
        CP_COMMIT();

        const unsigned* sA = smu + (it & 3) * (2 * GSTAGE);
        const unsigned* sB = sA + GSTAGE;
#pragma unroll
        for (int ks = 0; ks < 2; ks++) {
            unsigned a[4][4];
#pragma unroll
            for (int mf = 0; mf < 4; mf++) {
                uint2 a02 = *(const uint2*)&sA[(wm + mf * 16 + lq) * GST + ks * 8 + lr * 2];
                uint2 a13 = *(const uint2*)&sA[(wm + mf * 16 + 8 + lq) * GST + ks * 8 + lr * 2];
                a[mf][0] = a02.x; a[mf][1] = a13.x; a[mf][2] = a02.y; a[mf][3] = a13.y;
            }
#pragma unroll
            for (int nf = 0; nf < 8; nf++) {
                uint2 b = *(const uint2*)&sB[(wn + nf * 8 + lq) * GST + ks * 8 + lr * 2];
#pragma unroll
                for (int mf = 0; mf < 4; mf++)
                    mma_f16(acc[mf][nf], a[mf][0], a[mf][1], a[mf][2], a[mf][3],
                            b.x, b.y);
            }
        }
    }
#pragma unroll
    for (int mf = 0; mf < 4; mf++)
#pragma unroll
        for (int nf = 0; nf < 8; nf++) {
            float* c0 = C + (size_t)(bm + wm + mf * 16 + lq) * N + bn + wn + nf * 8 + lr * 2;
            c0[0] = acc[mf][nf][0]; c0[1] = acc[mf][nf][1];
            float* c1 = c0 + 8 * (size_t)N;
            c1[0] = acc[mf][nf][2]; c1[1] = acc[mf][nf][3];
        }
}

// ---------------- RMSNorm + rotary + V blend (2 tokens/block) -----------------
__global__ __launch_bounds__(256) void qkv_post(const float* __restrict__ qkv,
                                                const float* __restrict__ ve,
                                                const float* __restrict__ lambdas,
                                                unsigned* __restrict__ Qw,
                                                unsigned* __restrict__ Kw,
                                                unsigned* __restrict__ Vtw) {
    const int sb = threadIdx.x >> 7;          // sub-block: token within pair
    const int d  = threadIdx.x & 127;
    const int t  = blockIdx.x * 2 + sb;
    const int h  = blockIdx.y;
    const int lane = d & 31, wid = d >> 5;
    const float* base = qkv + (size_t)t * (3 * D_MODEL) + h * HDIM;

    float qv = base[d];
    float kv = base[D_MODEL + d];
    float vv = base[2 * D_MODEL + d];

    float s1 = qv * qv, s2 = kv * kv;
#pragma unroll
    for (int o = 16; o; o >>= 1) {
        s1 += __shfl_xor_sync(0xffffffffu, s1, o);
        s2 += __shfl_xor_sync(0xffffffffu, s2, o);
    }
    __shared__ float w1[2][4], w2[2][4];
    if (lane == 0) { w1[sb][wid] = s1; w2[sb][wid] = s2; }
    __syncthreads();
    float sq = w1[sb][0] + w1[sb][1] + w1[sb][2] + w1[sb][3];
    float sk = w2[sb][0] + w2[sb][1] + w2[sb][2] + w2[sb][3];
    const float eps = 1.1920929e-7f;
    float rq = rsqrtf(sq * (1.0f / 128.0f) + eps);
    float rk = rsqrtf(sk * (1.0f / 128.0f) + eps);

    __shared__ float qs[2][128], ks[2][128];
    qs[sb][d] = qv * rq; ks[sb][d] = kv * rk;
    __syncthreads();

    int j = d & 63;
    float ang = (j < 32) ? exp2f((float)j * (-10.0f / 31.0f)) : 0.0f;
    float theta = (float)t * ang;
    float c, s;
    sincosf(theta, &s, &c);

    float qo, ko;
    if (d < 64) {
        qo =  qs[sb][d] * c + qs[sb][d + 64] * s;
        ko =  ks[sb][d] * c + ks[sb][d + 64] * s;
    } else {
        qo = -qs[sb][d - 64] * s + qs[sb][d] * c;
        ko = -ks[sb][d - 64] * s + ks[sb][d] * c;
    }

    float l0 = lambdas[0], l1 = lambdas[1];
    float vo = l0 * vv + l1 * ve[(size_t)t * D_MODEL + h * HDIM + d];

    // V^T [h][d][t], fp16, word-permuted along s within 16-s groups
    {
        int ws = t >> 1;
        int gg = ws >> 3, pp = ws & 7;
        int iw = (gg << 3) | (((pp & 3) << 1) | (pp >> 2));
        size_t widx = ((size_t)(h * HDIM + d)) * (T_LEN / 2) + iw;
        ((__half*)Vtw)[widx * 2 + (t & 1)] = __float2half_rn(vo);
    }

    __syncthreads();                 // rotary reads of qs/ks done
    qs[sb][d] = qo * ATTN_SCALE;
    ks[sb][d] = ko;
    __syncthreads();

    if (d < 64) {                    // pack word w=d (elems 2d, 2d+1), permuted
        int p = d & 7, g = d >> 3;
        int iw = (g << 3) | (((p & 3) << 1) | (p >> 2));
        size_t rbw = ((size_t)h * T_LEN + t) * (HDIM / 2);
        Qw[rbw + iw] = f2h2(qs[sb][2 * d], qs[sb][2 * d + 1]);
        Kw[rbw + iw] = f2h2(ks[sb][2 * d], ks[sb][2 * d + 1]);
    }
}

// ---------------- fp16 mma causal flash attention, split-K (2 CTAs/SM) --------
// 128 thr, 4 warps, CTA = 64 q rows x half the key range. Static-shift softmax
// makes partials additive: each phase writes fp32 partial O + partial l.
#define KS  68                       // K tile row stride (64 words + 4)
#define KW  (64 * KS)
#define VTS 36                       // V^T tile row stride (32 words + 4)
#define VW  (128 * VTS)
#define ATTN_SMEM ((2 * KW + 2 * VW) * 4)
__global__ __launch_bounds__(128, 2) void attn_h(const unsigned* __restrict__ Q,
                                                 const unsigned* __restrict__ K,
                                                 const unsigned* __restrict__ Vt,
                                                 float* __restrict__ PO,
                                                 float* __restrict__ PL) {
    extern __shared__ unsigned sm[];

    const int h  = blockIdx.y;
    const int qi = (int)gridDim.x - 1 - (int)blockIdx.x;
    const int qb = qi * 64;
    const int nt = qi + 1;
    const int mid = (nt + 1) >> 1;
    const int ph = blockIdx.z;
    const int t0 = ph ? mid : 0;
    const int t1 = ph ? nt : mid;

    float* po = PO + (size_t)ph * T_LEN * D_MODEL;
    float* pl = PL + ph * (NHEAD * T_LEN);

    const int tid = threadIdx.x, wid = tid >> 5, lane = tid & 31;
    const int lq = lane >> 2, lr = lane & 3;
    const int qw = wid * 16;

    const unsigned* Khw = K + (size_t)h * T_LEN * (HDIM / 2);
    const unsigned* Vtwh = Vt + (size_t)h * HDIM * (T_LEN / 2);

    // persistent Q fragments: rows qb+qw+lq, +8 ; 8 k16-groups
    unsigned qa[8][4];
    {
        const unsigned* Qr0 = Q + ((size_t)h * T_LEN + qb + qw + lq) * (HDIM / 2);
        const unsigned* Qr1 = Qr0 + 8 * (HDIM / 2);
#pragma unroll
        for (int ks = 0; ks < 8; ks++) {
            uint2 a02 = *(const uint2*)&Qr0[ks * 8 + lr * 2];
            uint2 a13 = *(const uint2*)&Qr1[ks * 8 + lr * 2];
            qa[ks][0] = a02.x; qa[ks][1] = a13.x; qa[ks][2] = a02.y; qa[ks][3] = a13.y;
        }
    }

    float ofr[16][4];
#pragma unroll
    for (int nf = 0; nf < 16; nf++)
#pragma unroll
        for (int j = 0; j < 4; j++) ofr[nf][j] = 0.f;
    float l0 = 0.f, l1 = 0.f;

    auto issue_kv = [&](int s0, int buf) {
        unsigned* Kb = sm + buf * KW;
        unsigned* Vb = sm + 2 * KW + buf * VW;
        const int s0w = s0 >> 1;
#pragma unroll
        for (int p = 0; p < 8; p++) {
            int e = tid + 128 * p;
            int rk = e >> 4, ck = (e & 15) * 4;
            cp16(&Kb[rk * KS + ck], Khw + (size_t)(s0 + rk) * (HDIM / 2) + ck);
            int rv = e >> 3, cv = (e & 7) * 4;
            cp16(&Vb[rv * VTS + cv], Vtwh + (size_t)rv * (T_LEN / 2) + s0w + cv);
        }
    };

    if (t0 < t1) { issue_kv(t0 * 64, 0); }
    CP_COMMIT();

    for (int it = t0; it < t1; it++) {
        const int s0 = it * 64;
        const int buf = (it - t0) & 1;
        CP_WAIT(0);
        __syncthreads();                       // K,V (buf) visible; buf^1 free
        if (it + 1 < t1) issue_kv(s0 + 64, buf ^ 1);
        CP_COMMIT();

        const unsigned* Kb = sm + buf * KW;
        const unsigned* Vb = sm + 2 * KW + buf * VW;

        // ---- S = Q K^T (warp rows qw..qw+15) ----
        float sfr[8][4];
#pragma unroll
        for (int nf = 0; nf < 8; nf++)
#pragma unroll
            for (int j = 0; j < 4; j++) sfr[nf][j] = 0.f;
#pragma unroll
        for (int ks = 0; ks < 8; ks++) {
#pragma unroll
            for (int nf = 0; nf < 8; nf++) {
                uint2 b = *(const uint2*)&Kb[(nf * 8 + lq) * KS + ks * 8 + lr * 2];
                mma_f16(sfr[nf], qa[ks][0], qa[ks][1], qa[ks][2], qa[ks][3], b.x, b.y);
            }
        }

        // ---- masked static-shift softmax (no max, no rescale) ----
        const int q0 = qb + qw + lq, q1 = q0 + 8;
        const bool needmask = (s0 + 63) > (qb + qw);
        if (needmask) {
#pragma unroll
            for (int nf = 0; nf < 8; nf++) {
                int sA = s0 + nf * 8 + 2 * lr, sB = sA + 1;
                if (sA > q0) sfr[nf][0] = -1e30f;
                if (sB > q0) sfr[nf][1] = -1e30f;
                if (sA > q1) sfr[nf][2] = -1e30f;
                if (sB > q1) sfr[nf][3] = -1e30f;
            }
        }
        unsigned pu0[8], pu1[8];
#pragma unroll
        for (int nf = 0; nf < 8; nf++) {
            float p00 = fexp(sfr[nf][0] - CEXP);
            float p01 = fexp(sfr[nf][1] - CEXP);
            float p10 = fexp(sfr[nf][2] - CEXP);
            float p11 = fexp(sfr[nf][3] - CEXP);
            l0 += p00 + p01; l1 += p10 + p11;
            pu0[nf] = f2h2(p00, p01);
            pu1[nf] = f2h2(p10, p11);
        }

        // ---- O += P V : A = P (register-resident), B = V^T rows ------------
#pragma unroll
        for (int kk = 0; kk < 4; kk++) {
            unsigned a0 = pu0[2 * kk],     a1 = pu1[2 * kk];
            unsigned a2 = pu0[2 * kk + 1], a3 = pu1[2 * kk + 1];
#pragma unroll
            for (int nf = 0; nf < 16; nf++) {
                uint2 b = *(const uint2*)&Vb[(nf * 8 + lq) * VTS + kk * 8 + lr * 2];
                mma_f16(ofr[nf], a0, a1, a2, a3, b.x, b.y);
            }
        }
    }

    // ---- epilogue: quad-reduce partial sums, write fp32 partials -------------
    l0 += __shfl_xor_sync(0xffffffffu, l0, 1);
    l0 += __shfl_xor_sync(0xffffffffu, l0, 2);
    l1 += __shfl_xor_sync(0xffffffffu, l1, 1);
    l1 += __shfl_xor_sync(0xffffffffu, l1, 2);
    if (lr == 0) {
        pl[h * T_LEN + qb + qw + lq]     = l0;
        pl[h * T_LEN + qb + qw + lq + 8] = l1;
    }
    float* pr0 = po + (size_t)(qb + qw + lq) * D_MODEL + h * HDIM;
    float* pr1 = pr0 + 8 * (size_t)D_MODEL;
#pragma unroll
    for (int nf = 0; nf < 16; nf++) {
        int c = nf * 8 + 2 * lr;
        float2 v0; v0.x = ofr[nf][0]; v0.y = ofr[nf][1];
        float2 v1; v1.x = ofr[nf][2]; v1.y = ofr[nf][3];
        *(float2*)&pr0[c] = v0;
        *(float2*)&pr1[c] = v1;
    }
}

// ---------------- merge split-K partials -> fp16 permuted Y -------------------
__global__ __launch_bounds__(256) void merge_y(const float* __restrict__ PO,
                                               const float* __restrict__ PL,
                                               unsigned* __restrict__ Y) {
    int i = blockIdx.x * 256 + threadIdx.x;    // over T_LEN * 512 words
    int t = i >> 9;
    int wq = i & 511;
    int h = wq >> 6;
    int w = wq & 63;
    int p = w & 7, g = w >> 3;
    int iw = (g << 3) | (((p & 3) << 1) | (p >> 2));
    size_t base = (size_t)t * D_MODEL + h * HDIM + 2 * w;
    float2 a = *(const float2*)&PO[base];
    float2 b = *(const float2*)&PO[(size_t)T_LEN * D_MODEL + base];
    float l = PL[h * T_LEN + t] + PL[NHEAD * T_LEN + h * T_LEN + t];
    float inv = 1.0f / l;
    Y[(size_t)t * (D_MODEL / 2) + h * (HDIM / 2) + iw] =
        f2h2((a.x + b.x) * inv, (a.y + b.y) * inv);
}

// ---------------- launch ------------------------------------------------------
extern "C" void kernel_launch(void* const* d_in, const int* in_sizes, int n_in,
                              void* d_out, int out_size) {
    const float* x        = (const float*)d_in[0];
    const float* ve       = (const float*)d_in[1];
    const float* qkv_w    = (const float*)d_in[2];
    const float* lambdas  = (const float*)d_in[3];
    const float* c_proj_w = (const float*)d_in[4];
    float* out = (float*)d_out;

    float *p_qkv, *p_po, *p_pl;
    unsigned *p_q, *p_k, *p_v, *p_y, *p_xi, *p_wi, *p_cpi;
    cudaGetSymbolAddress((void**)&p_qkv, g_qkv);
    cudaGetSymbolAddress((void**)&p_q, g_q);
    cudaGetSymbolAddress((void**)&p_k, g_k);
    cudaGetSymbolAddress((void**)&p_v, g_v);
    cudaGetSymbolAddress((void**)&p_y, g_y);
    cudaGetSymbolAddress((void**)&p_xi, g_xi);
    cudaGetSymbolAddress((void**)&p_wi, g_wi);
    cudaGetSymbolAddress((void**)&p_cpi, g_cpi);
    cudaGetSymbolAddress((void**)&p_po, g_po);
    cudaGetSymbolAddress((void**)&p_pl, g_pl);

    static bool attr_set = false;
    if (!attr_set) {
        cudaFuncSetAttribute(gemm_h, cudaFuncAttributeMaxDynamicSharedMemorySize,
                             GEMM_SMEM);
        cudaFuncSetAttribute(attn_h, cudaFuncAttributeMaxDynamicSharedMemorySize,
                             ATTN_SMEM);
        attr_set = true;
    }

    // pre-pass conversions (fp32 -> permuted fp16 words)
    conv_h<<<1024, 256>>>(x, p_xi, T_LEN * D_MODEL / 16);
    conv_h<<<768, 256>>>(qkv_w, p_wi, 3 * D_MODEL * D_MODEL / 16);
    conv_h<<<256, 256>>>(c_proj_w, p_cpi, D_MODEL * D_MODEL / 16);

    // QKV projection
    gemm_h<<<dim3(3 * D_MODEL / 128, T_LEN / 128), 128, GEMM_SMEM>>>(
        p_xi, p_wi, p_qkv, T_LEN, 3 * D_MODEL, D_MODEL / 2);

    qkv_post<<<dim3(T_LEN / 2, NHEAD), 256>>>(p_qkv, ve, lambdas, p_q, p_k, p_v);

    // split-K attention: 2 phases over key range
    attn_h<<<dim3(T_LEN / 64, NHEAD, 2), 128, ATTN_SMEM>>>(p_q, p_k, p_v,
                                                           p_po, p_pl);
    merge_y<<<T_LEN * 512 / 256, 256>>>(p_po, p_pl, p_y);

    // output projection
    gemm_h<<<dim3(D_MODEL / 128, T_LEN / 128), 128, GEMM_SMEM>>>(
        p_y, p_cpi, out, T_LEN, D_MODEL, D_MODEL / 2);
}

// round 17
// speedup vs baseline: 1.5869x; 1.0392x over previous
#include <cuda_runtime.h>
#include <cuda_fp16.h>
#include <cstdint>

#define T_LEN   4096
#define D_MODEL 1024
#define NHEAD   8
#define HDIM    128
#define ATTN_SCALE 0.12f
#define CEXP    5.9f   // static softmax shift: |s| <= 15.36, exp(15.6-5.9) < fp16 max

// ---------------- fp16 mma helpers -------------------------------------------
__device__ __forceinline__ void mma_f16(float* d,
    unsigned a0, unsigned a1, unsigned a2, unsigned a3,
    unsigned b0, unsigned b1) {
    asm volatile("mma.sync.aligned.m16n8k16.row.col.f32.f16.f16.f32 "
        "{%0,%1,%2,%3},{%4,%5,%6,%7},{%8,%9},{%0,%1,%2,%3};"
        : "+f"(d[0]), "+f"(d[1]), "+f"(d[2]), "+f"(d[3])
        : "r"(a0), "r"(a1), "r"(a2), "r"(a3), "r"(b0), "r"(b1));
}
// pack two f32 -> f16x2 word {lo, hi}. PTX: cvt d, a, b -> hi=a, lo=b.
__device__ __forceinline__ unsigned f2h2(float lo, float hi) {
    unsigned r;
    asm("cvt.rn.f16x2.f32 %0, %1, %2;" : "=r"(r) : "f"(hi), "f"(lo));
    return r;
}
// fast exp: 1 MUL + 1 MUFU.EX2 (large negative -> 0)
__device__ __forceinline__ float fexp(float x) { return __expf(x); }

__device__ __forceinline__ void cp16(void* smem_ptr, const void* gptr) {
    unsigned sa = (unsigned)__cvta_generic_to_shared(smem_ptr);
    asm volatile("cp.async.cg.shared.global [%0], [%1], 16;" :: "r"(sa), "l"(gptr));
}
#define CP_COMMIT() asm volatile("cp.async.commit_group;")
#define CP_WAIT(N)  asm volatile("cp.async.wait_group %0;" :: "n"(N))

__device__ __forceinline__ void ldsm_x4(unsigned& r0, unsigned& r1,
                                        unsigned& r2, unsigned& r3,
                                        const unsigned* p) {
    unsigned a = (unsigned)__cvta_generic_to_shared(p);
    asm volatile("ldmatrix.sync.aligned.m8n8.x4.shared.b16 {%0,%1,%2,%3}, [%4];"
        : "=r"(r0), "=r"(r1), "=r"(r2), "=r"(r3) : "r"(a));
}

// ---------------- scratch (word = fp16x2) -------------------------------------
__device__ float    g_qkv[(size_t)T_LEN * 3 * D_MODEL];          // fp32 gemm out
__device__ unsigned g_q[(size_t)NHEAD * T_LEN * (HDIM / 2)];     // fp16, perm, *scale
__device__ unsigned g_k[(size_t)NHEAD * T_LEN * (HDIM / 2)];     // fp16, perm
__device__ unsigned g_v[(size_t)NHEAD * HDIM * (T_LEN / 2)];     // V^T fp16, s-perm
__device__ unsigned g_y[(size_t)T_LEN * (D_MODEL / 2)];          // fp16, NATURAL
__device__ unsigned g_xi[(size_t)T_LEN * (D_MODEL / 2)];         // fp16, NATURAL
__device__ unsigned g_wi[(size_t)3 * D_MODEL * (D_MODEL / 2)];   // fp16, NATURAL
__device__ unsigned g_cpi[(size_t)D_MODEL * (D_MODEL / 2)];      // fp16, NATURAL
__device__ float    g_po[(size_t)2 * T_LEN * D_MODEL];           // split-K partial O
__device__ float    g_pl[2 * NHEAD * T_LEN];                     // split-K partial l

// ---------------- pre-pass: fp32 -> fp16 words (natural layout) ---------------
__global__ __launch_bounds__(256) void conv_h(const float* __restrict__ in,
                                              unsigned* __restrict__ out, int ng) {
    int g = blockIdx.x * 256 + threadIdx.x;
    if (g >= ng) return;
    const float4* ip = (const float4*)(in + (size_t)g * 16);
    float4 v0 = ip[0], v1 = ip[1], v2 = ip[2], v3 = ip[3];
    uint4 o0, o1;
    o0.x = f2h2(v0.x, v0.y); o0.y = f2h2(v0.z, v0.w);
    o0.z = f2h2(v1.x, v1.y); o0.w = f2h2(v1.z, v1.w);
    o1.x = f2h2(v2.x, v2.y); o1.y = f2h2(v2.z, v2.w);
    o1.z = f2h2(v3.x, v3.y); o1.w = f2h2(v3.z, v3.w);
    uint4* op = (uint4*)(out + (size_t)g * 8);
    op[0] = o0; op[1] = o1;
}

// ---------------- fp16 NT GEMM via ldmatrix: C[M,N] = A[M,K] B[N,K]^T ---------
// 128 threads, 4 warps (2M x 2N), warp tile 64x64, BK=32 elems (16 words).
// Natural fp16 layout; fragments via ldmatrix.x4 (bank-conflict-free, GST=20).
#define GST 20
#define GSTAGE (128 * GST)
#define GEMM_SMEM (4 * 2 * GSTAGE * 4)
__global__ __launch_bounds__(128, 2) void gemm_h(const unsigned* __restrict__ A,
                                                 const unsigned* __restrict__ B,
                                                 float* __restrict__ C,
                                                 int M, int N, int Kw) {
    extern __shared__ unsigned smu[];
    const int bm = blockIdx.y * 128, bn = blockIdx.x * 128;
    const int tid = threadIdx.x;
    const int wid = tid >> 5, lane = tid & 31;
    const int wm = (wid >> 1) * 64, wn = (wid & 1) * 64;
    const int lq = lane >> 2, lr = lane & 3;
    const int lrow = lane & 15;            // ldmatrix row within 16-row group
    const int lhalf = (lane >> 4) * 4;     // ldmatrix k-half word offset

    float acc[4][8][4];
#pragma unroll
    for (int mf = 0; mf < 4; mf++)
#pragma unroll
        for (int nf = 0; nf < 8; nf++)
#pragma unroll
            for (int j = 0; j < 4; j++) acc[mf][nf][j] = 0.f;

    const int nk = Kw >> 4;

    auto issue = [&](int it, int buf) {
        unsigned* sA = smu + buf * (2 * GSTAGE);
        unsigned* sB = sA + GSTAGE;
        int k0 = it << 4;
#pragma unroll
        for (int p = 0; p < 4; p++) {
            int e = tid + 128 * p;
            int r = e >> 2, ch = (e & 3) * 4;
            cp16(&sA[r * GST + ch], A + (size_t)(bm + r) * Kw + k0 + ch);
            cp16(&sB[r * GST + ch], B + (size_t)(bn + r) * Kw + k0 + ch);
        }
    };

    issue(0, 0); CP_COMMIT();
    issue(1, 1); CP_COMMIT();
    issue(2, 2); CP_COMMIT();

    for (int it = 0; it < nk; it++) {
        CP_WAIT(2);
        __syncthreads();
        if (it + 3 < nk) issue(it + 3, (it + 3) & 3);
        CP_COMMIT();

        const unsigned* sA = smu + (it & 3) * (2 * GSTAGE);
        const unsigned* sB = sA + GSTAGE;
#pragma unroll
        for (int ks = 0; ks < 2; ks++) {
            unsigned a[4][4];
#pragma unroll
            for (int mf = 0; mf < 4; mf++)
                ldsm_x4(a[mf][0], a[mf][1], a[mf][2], a[mf][3],
                        &sA[(wm + mf * 16 + lrow) * GST + ks * 8 + lhalf]);
#pragma unroll
            for (int nfp = 0; nfp < 4; nfp++) {
                unsigned b0, b1, b2, b3;
                ldsm_x4(b0, b1, b2, b3,
                        &sB[(wn + nfp * 16 + lrow) * GST + ks * 8 + lhalf]);
#pragma unroll
                for (int mf = 0; mf < 4; mf++) {
                    mma_f16(acc[mf][2 * nfp],     a[mf][0], a[mf][1], a[mf][2], a[mf][3], b0, b2);
                    mma_f16(acc[mf][2 * nfp + 1], a[mf][0], a[mf][1], a[mf][2], a[mf][3], b1, b3);
                }
            }
        }
    }
#pragma unroll
    for (int mf = 0; mf < 4; mf++)
#pragma unroll
        for (int nf = 0; nf < 8; nf++) {
            float* c0 = C + (size_t)(bm + wm + mf * 16 + lq) * N + bn + wn + nf * 8 + lr * 2;
            c0[0] = acc[mf][nf][0]; c0[1] = acc[mf][nf][1];
            float* c1 = c0 + 8 * (size_t)N;
            c1[0] = acc[mf][nf][2]; c1[1] = acc[mf][nf][3];
        }
}

// ---------------- RMSNorm + rotary + V blend (2 tokens/block) -----------------
__global__ __launch_bounds__(256) void qkv_post(const float* __restrict__ qkv,
                                                const float* __restrict__ ve,
                                                const float* __restrict__ lambdas,
                                                unsigned* __restrict__ Qw,
                                                unsigned* __restrict__ Kw,
                                                unsigned* __restrict__ Vtw) {
    const int sb = threadIdx.x >> 7;
    const int d  = threadIdx.x & 127;
    const int t  = blockIdx.x * 2 + sb;
    const int h  = blockIdx.y;
    const int lane = d & 31, wid = d >> 5;
    const float* base = qkv + (size_t)t * (3 * D_MODEL) + h * HDIM;

    float qv = base[d];
    float kv = base[D_MODEL + d];
    float vv = base[2 * D_MODEL + d];

    float s1 = qv * qv, s2 = kv * kv;
#pragma unroll
    for (int o = 16; o; o >>= 1) {
        s1 += __shfl_xor_sync(0xffffffffu, s1, o);
        s2 += __shfl_xor_sync(0xffffffffu, s2, o);
    }
    __shared__ float w1[2][4], w2[2][4];
    if (lane == 0) { w1[sb][wid] = s1; w2[sb][wid] = s2; }
    __syncthreads();
    float sq = w1[sb][0] + w1[sb][1] + w1[sb][2] + w1[sb][3];
    float sk = w2[sb][0] + w2[sb][1] + w2[sb][2] + w2[sb][3];
    const float eps = 1.1920929e-7f;
    float rq = rsqrtf(sq * (1.0f / 128.0f) + eps);
    float rk = rsqrtf(sk * (1.0f / 128.0f) + eps);

    __shared__ float qs[2][128], ks[2][128];
    qs[sb][d] = qv * rq; ks[sb][d] = kv * rk;
    __syncthreads();

    int j = d & 63;
    float ang = (j < 32) ? exp2f((float)j * (-10.0f / 31.0f)) : 0.0f;
    float theta = (float)t * ang;
    float c, s;
    sincosf(theta, &s, &c);

    float qo, ko;
    if (d < 64) {
        qo =  qs[sb][d] * c + qs[sb][d + 64] * s;
        ko =  ks[sb][d] * c + ks[sb][d + 64] * s;
    } else {
        qo = -qs[sb][d - 64] * s + qs[sb][d] * c;
        ko = -ks[sb][d - 64] * s + ks[sb][d] * c;
    }

    float l0 = lambdas[0], l1 = lambdas[1];
    float vo = l0 * vv + l1 * ve[(size_t)t * D_MODEL + h * HDIM + d];

    // V^T [h][d][t], fp16, word-permuted along s within 16-s groups
    {
        int ws = t >> 1;
        int gg = ws >> 3, pp = ws & 7;
        int iw = (gg << 3) | (((pp & 3) << 1) | (pp >> 2));
        size_t widx = ((size_t)(h * HDIM + d)) * (T_LEN / 2) + iw;
        ((__half*)Vtw)[widx * 2 + (t & 1)] = __float2half_rn(vo);
    }

    __syncthreads();
    qs[sb][d] = qo * ATTN_SCALE;
    ks[sb][d] = ko;
    __syncthreads();

    if (d < 64) {                    // pack word w=d (elems 2d, 2d+1), permuted
        int p = d & 7, g = d >> 3;
        int iw = (g << 3) | (((p & 3) << 1) | (p >> 2));
        size_t rbw = ((size_t)h * T_LEN + t) * (HDIM / 2);
        Qw[rbw + iw] = f2h2(qs[sb][2 * d], qs[sb][2 * d + 1]);
        Kw[rbw + iw] = f2h2(ks[sb][2 * d], ks[sb][2 * d + 1]);
    }
}

// ---------------- fp16 mma causal flash attention, split-K (2 CTAs/SM) --------
#define KS  68
#define KW  (64 * KS)
#define VTS 36
#define VW  (128 * VTS)
#define ATTN_SMEM ((2 * KW + 2 * VW) * 4)
__global__ __launch_bounds__(128, 2) void attn_h(const unsigned* __restrict__ Q,
                                                 const unsigned* __restrict__ K,
                                                 const unsigned* __restrict__ Vt,
                                                 float* __restrict__ PO,
                                                 float* __restrict__ PL) {
    extern __shared__ unsigned sm[];

    const int h  = blockIdx.y;
    const int qi = (int)gridDim.x - 1 - (int)blockIdx.x;
    const int qb = qi * 64;
    const int nt = qi + 1;
    const int mid = (nt + 1) >> 1;
    const int ph = blockIdx.z;
    const int t0 = ph ? mid : 0;
    const int t1 = ph ? nt : mid;

    float* po = PO + (size_t)ph * T_LEN * D_MODEL;
    float* pl = PL + ph * (NHEAD * T_LEN);

    const int tid = threadIdx.x, wid = tid >> 5, lane = tid & 31;
    const int lq = lane >> 2, lr = lane & 3;
    const int qw = wid * 16;

    const unsigned* Khw = K + (size_t)h * T_LEN * (HDIM / 2);
    const unsigned* Vtwh = Vt + (size_t)h * HDIM * (T_LEN / 2);

    unsigned qa[8][4];
    {
        const unsigned* Qr0 = Q + ((size_t)h * T_LEN + qb + qw + lq) * (HDIM / 2);
        const unsigned* Qr1 = Qr0 + 8 * (HDIM / 2);
#pragma unroll
        for (int ks = 0; ks < 8; ks++) {
            uint2 a02 = *(const uint2*)&Qr0[ks * 8 + lr * 2];
            uint2 a13 = *(const uint2*)&Qr1[ks * 8 + lr * 2];
            qa[ks][0] = a02.x; qa[ks][1] = a13.x; qa[ks][2] = a02.y; qa[ks][3] = a13.y;
        }
    }

    float ofr[16][4];
#pragma unroll
    for (int nf = 0; nf < 16; nf++)
#pragma unroll
        for (int j = 0; j < 4; j++) ofr[nf][j] = 0.f;
    float l0 = 0.f, l1 = 0.f;

    auto issue_kv = [&](int s0, int buf) {
        unsigned* Kb = sm + buf * KW;
        unsigned* Vb = sm + 2 * KW + buf * VW;
        const int s0w = s0 >> 1;
#pragma unroll
        for (int p = 0; p < 8; p++) {
            int e = tid + 128 * p;
            int rk = e >> 4, ck = (e & 15) * 4;
            cp16(&Kb[rk * KS + ck], Khw + (size_t)(s0 + rk) * (HDIM / 2) + ck);
            int rv = e >> 3, cv = (e & 7) * 4;
            cp16(&Vb[rv * VTS + cv], Vtwh + (size_t)rv * (T_LEN / 2) + s0w + cv);
        }
    };

    if (t0 < t1) { issue_kv(t0 * 64, 0); }
    CP_COMMIT();

    for (int it = t0; it < t1; it++) {
        const int s0 = it * 64;
        const int buf = (it - t0) & 1;
        CP_WAIT(0);
        __syncthreads();
        if (it + 1 < t1) issue_kv(s0 + 64, buf ^ 1);
        CP_COMMIT();

        const unsigned* Kb = sm + buf * KW;
        const unsigned* Vb = sm + 2 * KW + buf * VW;

        float sfr[8][4];
#pragma unroll
        for (int nf = 0; nf < 8; nf++)
#pragma unroll
            for (int j = 0; j < 4; j++) sfr[nf][j] = 0.f;
#pragma unroll
        for (int ks = 0; ks < 8; ks++) {
#pragma unroll
            for (int nf = 0; nf < 8; nf++) {
                uint2 b = *(const uint2*)&Kb[(nf * 8 + lq) * KS + ks * 8 + lr * 2];
                mma_f16(sfr[nf], qa[ks][0], qa[ks][1], qa[ks][2], qa[ks][3], b.x, b.y);
            }
        }

        const int q0 = qb + qw + lq, q1 = q0 + 8;
        const bool needmask = (s0 + 63) > (qb + qw);
        if (needmask) {
#pragma unroll
            for (int nf = 0; nf < 8; nf++) {
                int sA = s0 + nf * 8 + 2 * lr, sB = sA + 1;
                if (sA > q0) sfr[nf][0] = -1e30f;
                if (sB > q0) sfr[nf][1] = -1e30f;
                if (sA > q1) sfr[nf][2] = -1e30f;
                if (sB > q1) sfr[nf][3] = -1e30f;
            }
        }
        unsigned pu0[8], pu1[8];
#pragma unroll
        for (int nf = 0; nf < 8; nf++) {
            float p00 = fexp(sfr[nf][0] - CEXP);
            float p01 = fexp(sfr[nf][1] - CEXP);
            float p10 = fexp(sfr[nf][2] - CEXP);
            float p11 = fexp(sfr[nf][3] - CEXP);
            l0 += p00 + p01; l1 += p10 + p11;
            pu0[nf] = f2h2(p00, p01);
            pu1[nf] = f2h2(p10, p11);
        }

#pragma unroll
        for (int kk = 0; kk < 4; kk++) {
            unsigned a0 = pu0[2 * kk],     a1 = pu1[2 * kk];
            unsigned a2 = pu0[2 * kk + 1], a3 = pu1[2 * kk + 1];
#pragma unroll
            for (int nf = 0; nf < 16; nf++) {
                uint2 b = *(const uint2*)&Vb[(nf * 8 + lq) * VTS + kk * 8 + lr * 2];
                mma_f16(ofr[nf], a0, a1, a2, a3, b.x, b.y);
            }
        }
    }

    // ---- epilogue: quad-reduce partial sums, write fp32 partials -------------
    l0 += __shfl_xor_sync(0xffffffffu, l0, 1);
    l0 += __shfl_xor_sync(0xffffffffu, l0, 2);
    l1 += __shfl_xor_sync(0xffffffffu, l1, 1);
    l1 += __shfl_xor_sync(0xffffffffu, l1, 2);
    if (lr == 0) {
        pl[h * T_LEN + qb + qw + lq]     = l0;
        pl[h * T_LEN + qb + qw + lq + 8] = l1;
    }
    float* pr0 = po + (size_t)(qb + qw + lq) * D_MODEL + h * HDIM;
    float* pr1 = pr0 + 8 * (size_t)D_MODEL;
#pragma unroll
    for (int nf = 0; nf < 16; nf++) {
        int c = nf * 8 + 2 * lr;
        float2 v0; v0.x = ofr[nf][0]; v0.y = ofr[nf][1];
        float2 v1; v1.x = ofr[nf][2]; v1.y = ofr[nf][3];
        *(float2*)&pr0[c] = v0;
        *(float2*)&pr1[c] = v1;
    }
}

// ---------------- merge split-K partials -> fp16 NATURAL Y --------------------
__global__ __launch_bounds__(256) void merge_y(const float* __restrict__ PO,
                                               const float* __restrict__ PL,
                                               unsigned* __restrict__ Y) {
    int i = blockIdx.x * 256 + threadIdx.x;    // over T_LEN * 512 words
    int t = i >> 9;
    int wq = i & 511;
    int h = wq >> 6;
    int w = wq & 63;
    size_t base = (size_t)t * D_MODEL + h * HDIM + 2 * w;
    float2 a = *(const float2*)&PO[base];
    float2 b = *(const float2*)&PO[(size_t)T_LEN * D_MODEL + base];
    float l = PL[h * T_LEN + t] + PL[NHEAD * T_LEN + h * T_LEN + t];
    float inv = 1.0f / l;
    Y[(size_t)t * (D_MODEL / 2) + h * (HDIM / 2) + w] =
        f2h2((a.x + b.x) * inv, (a.y + b.y) * inv);
}

// ---------------- launch ------------------------------------------------------
extern "C" void kernel_launch(void* const* d_in, const int* in_sizes, int n_in,
                              void* d_out, int out_size) {
    const float* x        = (const float*)d_in[0];
    const float* ve       = (const float*)d_in[1];
    const float* qkv_w    = (const float*)d_in[2];
    const float* lambdas  = (const float*)d_in[3];
    const float* c_proj_w = (const float*)d_in[4];
    float* out = (float*)d_out;

    float *p_qkv, *p_po, *p_pl;
    unsigned *p_q, *p_k, *p_v, *p_y, *p_xi, *p_wi, *p_cpi;
    cudaGetSymbolAddress((void**)&p_qkv, g_qkv);
    cudaGetSymbolAddress((void**)&p_q, g_q);
    cudaGetSymbolAddress((void**)&p_k, g_k);
    cudaGetSymbolAddress((void**)&p_v, g_v);
    cudaGetSymbolAddress((void**)&p_y, g_y);
    cudaGetSymbolAddress((void**)&p_xi, g_xi);
    cudaGetSymbolAddress((void**)&p_wi, g_wi);
    cudaGetSymbolAddress((void**)&p_cpi, g_cpi);
    cudaGetSymbolAddress((void**)&p_po, g_po);
    cudaGetSymbolAddress((void**)&p_pl, g_pl);

    static bool attr_set = false;
    if (!attr_set) {
        cudaFuncSetAttribute(gemm_h, cudaFuncAttributeMaxDynamicSharedMemorySize,
                             GEMM_SMEM);
        cudaFuncSetAttribute(attn_h, cudaFuncAttributeMaxDynamicSharedMemorySize,
                             ATTN_SMEM);
        attr_set = true;
    }

    // pre-pass conversions (fp32 -> fp16 natural)
    conv_h<<<1024, 256>>>(x, p_xi, T_LEN * D_MODEL / 16);
    conv_h<<<768, 256>>>(qkv_w, p_wi, 3 * D_MODEL * D_MODEL / 16);
    conv_h<<<256, 256>>>(c_proj_w, p_cpi, D_MODEL * D_MODEL / 16);

    // QKV projection
    gemm_h<<<dim3(3 * D_MODEL / 128, T_LEN / 128), 128, GEMM_SMEM>>>(
        p_xi, p_wi, p_qkv, T_LEN, 3 * D_MODEL, D_MODEL / 2);

    qkv_post<<<dim3(T_LEN / 2, NHEAD), 256>>>(p_qkv, ve, lambdas, p_q, p_k, p_v);

    // split-K attention: 2 phases over key range
    attn_h<<<dim3(T_LEN / 64, NHEAD, 2), 128, ATTN_SMEM>>>(p_q, p_k, p_v,
                                                           p_po, p_pl);
    merge_y<<<T_LEN * 512 / 256, 256>>>(p_po, p_pl, p_y);

    // output projection
    gemm_h<<<dim3(D_MODEL / 128, T_LEN / 128), 128, GEMM_SMEM>>>(
        p_y, p_cpi, out, T_LEN, D_MODEL, D_MODEL / 2);
}